// round 7
// baseline (speedup 1.0000x reference)
#include <cuda_runtime.h>
#include <math.h>

#define Bn 12
#define HW1 45056           // 128*352
#define N5 11264            // 64*176
#define W5i 176
#define BEVC 64
#define OUT_MAIN (12*128*128*128)   // 25165824

typedef unsigned long long u64;

// packed f32x2 helpers (sm_103a)
__device__ __forceinline__ u64 pack2(float lo, float hi) {
    u64 r; asm("mov.b64 %0, {%1, %2};" : "=l"(r) : "f"(lo), "f"(hi)); return r;
}
__device__ __forceinline__ void fma2(u64 &d, u64 a, u64 b) {
    asm("fma.rn.f32x2 %0, %1, %2, %0;" : "+l"(d) : "l"(a), "l"(b));
}
__device__ __forceinline__ float2 unpack2(u64 v) {
    float2 r; asm("mov.b64 {%0, %1}, %2;" : "=f"(r.x), "=f"(r.y) : "l"(v)); return r;
}

// BEV scratch, channels-last: [B][128][128][64]
__device__ float g_bev[Bn * 128 * 128 * BEVC];
__device__ int   g_sidx[Bn * N5];
__device__ float g_swf [Bn * N5];
// transposed conv weights: [kk 9][ic 64][oc 128]
__device__ float g_wt[9 * 64 * 128];

// ---------------------------------------------------------------------------
// kWt: transpose main conv weights into g_wt  (tiny)
// ---------------------------------------------------------------------------
__global__ void kWt(const float* __restrict__ w)
{
    int i = blockIdx.x * 256 + threadIdx.x;
    if (i < 9*64*128) {
        int oc = i & 127;
        int t  = i >> 7;
        int ic = t & 63;
        int kk = t >> 6;
        g_wt[i] = w[(oc*64 + ic)*9 + kk];
    }
}

// ---------------------------------------------------------------------------
// Kernel A: fused skip path, 2 pixels per thread.
// ---------------------------------------------------------------------------
__global__ __launch_bounds__(128, 2)
void kA(const float* __restrict__ stage1,
        const float* __restrict__ w1, const float* __restrict__ g1, const float* __restrict__ b1,
        const float* __restrict__ w2, const float* __restrict__ g2, const float* __restrict__ b2,
        float* __restrict__ skip_out)
{
    __shared__ __align__(16) float w1T[64*64];   // [c][o]
    __shared__ __align__(16) float w2T[64*32];   // [o][s]
    __shared__ float sg1[64], sb1[64], sg2[32], sb2[32];
    int tid = threadIdx.x;
    for (int i = tid; i < 64*64; i += 128) { int o = i & 63, c = i >> 6; w1T[c*64+o] = w1[o*64+c]; }
    for (int i = tid; i < 64*32; i += 128) { int s = i & 31, o = i >> 5; w2T[o*32+s] = w2[s*64+o]; }
    if (tid < 64) { sg1[tid] = g1[tid]; sb1[tid] = b1[tid]; }
    if (tid < 32) { sg2[tid] = g2[tid]; sb2[tid] = b2[tid]; }
    __syncthreads();

    int gid = blockIdx.x * 256 + tid;
    int b = gid / HW1;
    int p = gid - b * HW1;
    const float* xin = stage1 + (size_t)b * 64 * HW1 + p;

    u64 acc[2][32];
    #pragma unroll
    for (int q = 0; q < 32; q++) { acc[0][q] = 0ull; acc[1][q] = 0ull; }

    const ulonglong2* w1T2 = (const ulonglong2*)w1T;
    for (int c = 0; c < 64; c++) {
        const float* xc = xin + (size_t)c * HW1;
        u64 x0 = pack2(xc[0],   xc[0]);
        u64 x1 = pack2(xc[128], xc[128]);
        #pragma unroll
        for (int q = 0; q < 16; q++) {
            ulonglong2 wp = w1T2[c*16 + q];
            fma2(acc[0][q*2+0], x0, wp.x);
            fma2(acc[0][q*2+1], x0, wp.y);
            fma2(acc[1][q*2+0], x1, wp.x);
            fma2(acc[1][q*2+1], x1, wp.y);
        }
    }

    const ulonglong2* w2T2 = (const ulonglong2*)w2T;
    #pragma unroll
    for (int px = 0; px < 2; px++) {
        u64 sacc2[16];
        #pragma unroll
        for (int s = 0; s < 16; s++) sacc2[s] = 0ull;
        #pragma unroll
        for (int q = 0; q < 32; q++) {
            float2 a = unpack2(acc[px][q]);
            int o = 2*q;
            float v0 = fmaxf(a.x * sg1[o]   + sb1[o],   0.f);
            float v1 = fmaxf(a.y * sg1[o+1] + sb1[o+1], 0.f);
            u64 v0p = pack2(v0, v0);
            u64 v1p = pack2(v1, v1);
            #pragma unroll
            for (int s4 = 0; s4 < 8; s4++) {
                ulonglong2 wp0 = w2T2[o*8 + s4];
                fma2(sacc2[s4*2+0], v0p, wp0.x);
                fma2(sacc2[s4*2+1], v0p, wp0.y);
            }
            #pragma unroll
            for (int s4 = 0; s4 < 8; s4++) {
                ulonglong2 wp1 = w2T2[(o+1)*8 + s4];
                fma2(sacc2[s4*2+0], v1p, wp1.x);
                fma2(sacc2[s4*2+1], v1p, wp1.y);
            }
        }
        float* op = skip_out + (size_t)b * 32 * HW1 + p + px * 128;
        #pragma unroll
        for (int s = 0; s < 16; s++) {
            float2 a = unpack2(sacc2[s]);
            op[(size_t)(2*s+0) * HW1] = fmaxf(a.x * sg2[2*s+0] + sb2[2*s+0], 0.f);
            op[(size_t)(2*s+1) * HW1] = fmaxf(a.y * sg2[2*s+1] + sb2[2*s+1], 0.f);
        }
    }
}

// ---------------------------------------------------------------------------
// Kernel B1: depth head. 48-channel GEMM + softmax depth + geometry.
// ---------------------------------------------------------------------------
__global__ __launch_bounds__(128, 4)
void kB1(const float* __restrict__ stage5,
         const float* __restrict__ wd, const float* __restrict__ gd, const float* __restrict__ bd,
         const float* __restrict__ intr, const float* __restrict__ extr)
{
    __shared__ __align__(16) float ws[64*48];
    __shared__ float sgd[48], sbd[48];
    int tid = threadIdx.x;
    if (tid < 48) { sgd[tid] = gd[tid]; sbd[tid] = bd[tid]; }
    int b = blockIdx.x / 88;
    int p = (blockIdx.x - b * 88) * 128 + tid;
    const float* xin = stage5 + (size_t)b * 512 * N5 + p;

    u64 acc2[24];
    #pragma unroll
    for (int i = 0; i < 24; i++) acc2[i] = 0ull;

    for (int c0 = 0; c0 < 512; c0 += 64) {
        __syncthreads();
        for (int i = tid; i < 64*48; i += 128) {
            int o = i % 48; int c = i / 48;
            ws[c*48 + o] = wd[o*512 + c0 + c];
        }
        __syncthreads();
        const ulonglong2* ws2 = (const ulonglong2*)ws;
        for (int c = 0; c < 64; c++) {
            float xv = xin[(size_t)(c0 + c) * N5];
            u64 xv2 = pack2(xv, xv);
            #pragma unroll
            for (int q = 0; q < 12; q++) {
                ulonglong2 wp = ws2[c*12 + q];
                fma2(acc2[q*2+0], xv2, wp.x);
                fma2(acc2[q*2+1], xv2, wp.y);
            }
        }
    }

    float m = -1e30f;
    #pragma unroll
    for (int q = 0; q < 24; q++) {
        float2 a = unpack2(acc2[q]);
        int j = 2*q;
        m = fmaxf(m, fmaxf(10.f * (a.x * sgd[j] + sbd[j]),
                           10.f * (a.y * sgd[j+1] + sbd[j+1])));
    }
    const float lstep = 0.08711371545f;  // ln(60)/47
    float sum = 0.f, dsum = 0.f;
    #pragma unroll
    for (int q = 0; q < 24; q++) {
        float2 a = unpack2(acc2[q]);
        int j = 2*q;
        float l0 = 10.f * (a.x * sgd[j]   + sbd[j]);
        float l1 = 10.f * (a.y * sgd[j+1] + sbd[j+1]);
        float e0 = __expf(l0 - m);
        float e1 = __expf(l1 - m);
        sum  += e0 + e1;
        dsum += e0 * __expf((float)j * lstep) + e1 * __expf((float)(j+1) * lstep);
    }
    float depth = dsum / sum;
    depth = fminf(fmaxf(depth, 1.0f), 65.0f);

    const float* K = intr + b * 9;
    float a00=K[0],a01=K[1],a02=K[2],a10=K[3],a11=K[4],a12=K[5],a20=K[6],a21=K[7],a22=K[8];
    float det = a00*(a11*a22 - a12*a21) - a01*(a10*a22 - a12*a20) + a02*(a10*a21 - a11*a20);
    float id = 1.0f / det;
    float i00 = (a11*a22 - a12*a21) * id;
    float i01 = (a02*a21 - a01*a22) * id;
    float i02 = (a01*a12 - a02*a11) * id;
    float i10 = (a12*a20 - a10*a22) * id;
    float i11 = (a00*a22 - a02*a20) * id;
    float i12 = (a02*a10 - a00*a12) * id;
    float i20 = (a10*a21 - a11*a20) * id;
    float i21 = (a01*a20 - a00*a21) * id;
    float i22 = (a00*a11 - a01*a10) * id;

    float py = (float)(p / W5i);
    float px = (float)(p - (p / W5i) * W5i);
    float cx = depth * (i00*px + i01*py + i02);
    float cy = depth * (i10*px + i11*py + i12);
    float cz = depth * (i20*px + i21*py + i22);

    const float* T = extr + b * 16;
    float ex = T[0]*cx + T[1]*cy + T[2]*cz  + T[3];
    float ey = T[4]*cx + T[5]*cy + T[6]*cz  + T[7];
    float ez = T[8]*cx + T[9]*cy + T[10]*cz + T[11];

    bool ev = (ex >= -51.2f) & (ex < 51.2f) & (ey >= -51.2f) & (ey < 51.2f)
            & (ez >= -5.0f)  & (ez < 3.0f);
    int bx = (int)floorf(ex / 0.4f + 64.0f);
    int by = (int)floorf(ey / 0.4f + 64.0f);
    bool gv = (bx >= 0) & (bx < 128) & (by >= 0) & (by < 128);

    int idx = -1; float wf = 0.f;
    if (ev & gv) {
        idx = ((b * 128 + by) * 128 + bx) * BEVC;
        wf = __expf(-0.05f * fabsf(ez));
    }
    g_sidx[b * N5 + p] = idx;
    g_swf [b * N5 + p] = wf;
}

// ---------------------------------------------------------------------------
// Kernel B2: reduced-feature GEMM (64 out) + scatter-add, 2 pixels/thread.
// ---------------------------------------------------------------------------
__global__ __launch_bounds__(128, 2)
void kB2(const float* __restrict__ stage5,
         const float* __restrict__ w5, const float* __restrict__ g5, const float* __restrict__ b5)
{
    __shared__ __align__(16) float ws[64*64];   // [c][o]
    __shared__ float sg[64], sb[64];
    int tid = threadIdx.x;
    if (tid < 64) { sg[tid] = g5[tid]; sb[tid] = b5[tid]; }
    int b = blockIdx.x / 44;
    int p = (blockIdx.x - b * 44) * 256 + tid;
    const float* xin = stage5 + (size_t)b * 512 * N5 + p;

    u64 acc[2][32];
    #pragma unroll
    for (int q = 0; q < 32; q++) { acc[0][q] = 0ull; acc[1][q] = 0ull; }

    for (int c0 = 0; c0 < 512; c0 += 64) {
        __syncthreads();
        for (int i = tid; i < 64*64; i += 128) {
            int o = i & 63; int c = i >> 6;
            ws[c*64 + o] = w5[o*512 + c0 + c];
        }
        __syncthreads();
        const ulonglong2* ws2 = (const ulonglong2*)ws;
        for (int c = 0; c < 64; c++) {
            const float* xc = xin + (size_t)(c0 + c) * N5;
            u64 x0 = pack2(xc[0],   xc[0]);
            u64 x1 = pack2(xc[128], xc[128]);
            #pragma unroll
            for (int q = 0; q < 16; q++) {
                ulonglong2 wp = ws2[c*16 + q];
                fma2(acc[0][q*2+0], x0, wp.x);
                fma2(acc[0][q*2+1], x0, wp.y);
                fma2(acc[1][q*2+0], x1, wp.x);
                fma2(acc[1][q*2+1], x1, wp.y);
            }
        }
    }

    #pragma unroll
    for (int px = 0; px < 2; px++) {
        int pp = p + px * 128;
        int idx = g_sidx[b * N5 + pp];
        float wf = g_swf[b * N5 + pp];
        if (idx >= 0) {
            float* cell = g_bev + idx;
            #pragma unroll
            for (int q = 0; q < 32; q++) {
                float2 a = unpack2(acc[px][q]);
                float r0 = fmaxf(a.x * sg[2*q+0] + sb[2*q+0], 0.f) * wf;
                float r1 = fmaxf(a.y * sg[2*q+1] + sb[2*q+1], 0.f) * wf;
                atomicAdd(cell + 2*q+0, r0);
                atomicAdd(cell + 2*q+1, r1);
            }
        }
    }
}

// ---------------------------------------------------------------------------
// Kernel C v3: 3x3 conv (64->128) + BN + ReLU.
// 32x16 spatial tile, 512 threads (1 px/thread, 16 warps/SM), 64 oc/block,
// double-buffered per-kk weight staging from transposed g_wt.
// ---------------------------------------------------------------------------
__global__ __launch_bounds__(512)
void kC(const float* __restrict__ g, const float* __restrict__ bb,
        float* __restrict__ out)
{
    extern __shared__ __align__(16) float sm[];
    float* sin_ = sm;               // [ic 64][cell 612]  (18 x 34 tile)
    float* wbuf = sm + 64*612;      // [2][ic 64][oc 64]
    int tid = threadIdx.x;
    int tx = tid & 31, ty = tid >> 5;        // ty 0..15
    int x0 = blockIdx.x * 32, y0 = blockIdx.y * 16;
    int bz = blockIdx.z;
    int b = bz >> 1;
    int oc0 = (bz & 1) * 64;

    // input tile (with halo, zero padded) -> shared
    const float4* bev4 = (const float4*)g_bev;
    for (int i = tid; i < 612*16; i += 512) {
        int icg = i & 15;
        int cell = i >> 4;
        int iy = cell / 34, ix = cell - iy * 34;
        int gy = y0 + iy - 1, gx = x0 + ix - 1;
        float4 v = make_float4(0.f, 0.f, 0.f, 0.f);
        if (gy >= 0 && gy < 128 && gx >= 0 && gx < 128)
            v = bev4[((((size_t)b * 128 + gy) * 128 + gx) << 4) + icg];
        sin_[(icg*4+0)*612 + cell] = v.x;
        sin_[(icg*4+1)*612 + cell] = v.y;
        sin_[(icg*4+2)*612 + cell] = v.z;
        sin_[(icg*4+3)*612 + cell] = v.w;
    }
    // stage kk=0 weights
    for (int i = tid; i < 4096; i += 512)
        wbuf[i] = g_wt[((i >> 6) << 7) + oc0 + (i & 63)];
    __syncthreads();

    u64 acc[32];
    #pragma unroll
    for (int q = 0; q < 32; q++) acc[q] = 0ull;

    for (int kk = 0; kk < 9; kk++) {
        int buf = kk & 1;
        if (kk < 8) {
            int nb = buf ^ 1;
            for (int i = tid; i < 4096; i += 512)
                wbuf[nb*4096 + i] = g_wt[(((kk+1)*64 + (i >> 6)) << 7) + oc0 + (i & 63)];
        }
        int ky = kk / 3, kx = kk - ky*3;
        int base = (ty + ky) * 34 + tx + kx;
        const ulonglong2* wb = (const ulonglong2*)(wbuf + buf*4096);
        #pragma unroll 2
        for (int ic = 0; ic < 64; ic++) {
            float xv = sin_[ic * 612 + base];
            u64 xp = pack2(xv, xv);
            const ulonglong2* wrow = wb + ic*16;
            #pragma unroll
            for (int q = 0; q < 16; q++) {
                ulonglong2 wv = wrow[q];
                fma2(acc[2*q+0], xp, wv.x);
                fma2(acc[2*q+1], xp, wv.y);
            }
        }
        __syncthreads();
    }

    float* op = out + (((size_t)b * 128 + oc0) * 128 + (y0 + ty)) * 128 + (x0 + tx);
    #pragma unroll
    for (int q = 0; q < 32; q++) {
        float2 a = unpack2(acc[q]);
        int o = 2*q;
        op[(size_t)(o+0) * 16384] = fmaxf(a.x * g[oc0 + o]     + bb[oc0 + o],     0.f);
        op[(size_t)(o+1) * 16384] = fmaxf(a.y * g[oc0 + o + 1] + bb[oc0 + o + 1], 0.f);
    }
}

// ---------------------------------------------------------------------------
extern "C" void kernel_launch(void* const* d_in, const int* in_sizes, int n_in,
                              void* d_out, int out_size)
{
    const float* stage1 = (const float*)d_in[0];
    const float* stage5 = (const float*)d_in[1];
    const float* intr   = (const float*)d_in[2];
    const float* extr   = (const float*)d_in[3];
    const float* red1_w = (const float*)d_in[4];
    const float* red1_g = (const float*)d_in[5];
    const float* red1_b = (const float*)d_in[6];
    const float* skip_w = (const float*)d_in[7];
    const float* skip_g = (const float*)d_in[8];
    const float* skip_b = (const float*)d_in[9];
    const float* red5_w = (const float*)d_in[10];
    const float* red5_g = (const float*)d_in[11];
    const float* red5_b = (const float*)d_in[12];
    const float* dep5_w = (const float*)d_in[13];
    const float* dep5_g = (const float*)d_in[14];
    const float* dep5_b = (const float*)d_in[15];
    const float* main_w = (const float*)d_in[16];
    const float* main_g = (const float*)d_in[17];
    const float* main_b = (const float*)d_in[18];

    float* out_main = (float*)d_out;
    float* out_skip = (float*)d_out + OUT_MAIN;

    // side stream + events (created once; creation is not a captured op)
    static cudaStream_t s1 = nullptr;
    static cudaEvent_t eFork = nullptr, eJoin = nullptr;
    if (!s1) {
        cudaStreamCreateWithFlags(&s1, cudaStreamNonBlocking);
        cudaEventCreateWithFlags(&eFork, cudaEventDisableTiming);
        cudaEventCreateWithFlags(&eJoin, cudaEventDisableTiming);
    }

    // zero BEV scratch (critical path start)
    void* bevPtr = nullptr;
    cudaGetSymbolAddress(&bevPtr, g_bev);
    cudaMemsetAsync(bevPtr, 0, sizeof(float) * (size_t)Bn * 128 * 128 * BEVC);

    // fork: skip path runs concurrently on s1
    cudaEventRecord(eFork, 0);
    cudaStreamWaitEvent(s1, eFork, 0);
    kA<<<(Bn * HW1) / 256, 128, 0, s1>>>(stage1, red1_w, red1_g, red1_b,
                                         skip_w, skip_g, skip_b, out_skip);
    cudaEventRecord(eJoin, s1);

    // critical path on capture stream
    kWt<<<(9*64*128 + 255)/256, 256>>>(main_w);
    kB1<<<Bn * 88, 128>>>(stage5, dep5_w, dep5_g, dep5_b, intr, extr);
    kB2<<<Bn * 44, 128>>>(stage5, red5_w, red5_g, red5_b);

    // join before kC (kA finishes well before kB2 does)
    cudaStreamWaitEvent(0, eJoin, 0);

    // BEV conv (32x16 tile, 512 threads, 64 oc/block)
    int smem = (64*612 + 2*4096) * sizeof(float);   // 189440
    cudaFuncSetAttribute(kC, cudaFuncAttributeMaxDynamicSharedMemorySize, smem);
    dim3 gridC(4, 8, Bn * 2);
    kC<<<gridC, 512, smem>>>(main_g, main_b, out_main);
}

// round 8
// speedup vs baseline: 1.0584x; 1.0584x over previous
#include <cuda_runtime.h>
#include <math.h>

#define Bn 12
#define HW1 45056           // 128*352
#define N5 11264            // 64*176
#define W5i 176
#define BEVC 64
#define OUT_MAIN (12*128*128*128)   // 25165824

typedef unsigned long long u64;

// packed f32x2 helpers (sm_103a)
__device__ __forceinline__ u64 pack2(float lo, float hi) {
    u64 r; asm("mov.b64 %0, {%1, %2};" : "=l"(r) : "f"(lo), "f"(hi)); return r;
}
__device__ __forceinline__ void fma2(u64 &d, u64 a, u64 b) {
    asm("fma.rn.f32x2 %0, %1, %2, %0;" : "+l"(d) : "l"(a), "l"(b));
}
__device__ __forceinline__ float2 unpack2(u64 v) {
    float2 r; asm("mov.b64 {%0, %1}, %2;" : "=f"(r.x), "=f"(r.y) : "l"(v)); return r;
}

// BEV scratch, channels-last: [B][128][128][64]
__device__ float g_bev[Bn * 128 * 128 * BEVC];
__device__ int   g_sidx[Bn * N5];
__device__ float g_swf [Bn * N5];
// transposed conv weights: [kk 9][ic 64][oc 128]
__device__ float g_wt[9 * 64 * 128];

// ---------------------------------------------------------------------------
// kWt: transpose main conv weights into g_wt  (tiny)
// ---------------------------------------------------------------------------
__global__ void kWt(const float* __restrict__ w)
{
    int i = blockIdx.x * 256 + threadIdx.x;
    if (i < 9*64*128) {
        int oc = i & 127;
        int t  = i >> 7;
        int ic = t & 63;
        int kk = t >> 6;
        g_wt[i] = w[(oc*64 + ic)*9 + kk];
    }
}

// ---------------------------------------------------------------------------
// Kernel A: fused skip path, 2 pixels per thread.  (proven R3 version)
// ---------------------------------------------------------------------------
__global__ __launch_bounds__(128, 2)
void kA(const float* __restrict__ stage1,
        const float* __restrict__ w1, const float* __restrict__ g1, const float* __restrict__ b1,
        const float* __restrict__ w2, const float* __restrict__ g2, const float* __restrict__ b2,
        float* __restrict__ skip_out)
{
    __shared__ __align__(16) float w1T[64*64];   // [c][o]
    __shared__ __align__(16) float w2T[64*32];   // [o][s]
    __shared__ float sg1[64], sb1[64], sg2[32], sb2[32];
    int tid = threadIdx.x;
    for (int i = tid; i < 64*64; i += 128) { int o = i & 63, c = i >> 6; w1T[c*64+o] = w1[o*64+c]; }
    for (int i = tid; i < 64*32; i += 128) { int s = i & 31, o = i >> 5; w2T[o*32+s] = w2[s*64+o]; }
    if (tid < 64) { sg1[tid] = g1[tid]; sb1[tid] = b1[tid]; }
    if (tid < 32) { sg2[tid] = g2[tid]; sb2[tid] = b2[tid]; }
    __syncthreads();

    int gid = blockIdx.x * 256 + tid;
    int b = gid / HW1;
    int p = gid - b * HW1;
    const float* xin = stage1 + (size_t)b * 64 * HW1 + p;

    u64 acc[2][32];
    #pragma unroll
    for (int q = 0; q < 32; q++) { acc[0][q] = 0ull; acc[1][q] = 0ull; }

    const ulonglong2* w1T2 = (const ulonglong2*)w1T;
    for (int c = 0; c < 64; c++) {
        const float* xc = xin + (size_t)c * HW1;
        u64 x0 = pack2(xc[0],   xc[0]);
        u64 x1 = pack2(xc[128], xc[128]);
        #pragma unroll
        for (int q = 0; q < 16; q++) {
            ulonglong2 wp = w1T2[c*16 + q];
            fma2(acc[0][q*2+0], x0, wp.x);
            fma2(acc[0][q*2+1], x0, wp.y);
            fma2(acc[1][q*2+0], x1, wp.x);
            fma2(acc[1][q*2+1], x1, wp.y);
        }
    }

    const ulonglong2* w2T2 = (const ulonglong2*)w2T;
    #pragma unroll
    for (int px = 0; px < 2; px++) {
        u64 sacc2[16];
        #pragma unroll
        for (int s = 0; s < 16; s++) sacc2[s] = 0ull;
        #pragma unroll
        for (int q = 0; q < 32; q++) {
            float2 a = unpack2(acc[px][q]);
            int o = 2*q;
            float v0 = fmaxf(a.x * sg1[o]   + sb1[o],   0.f);
            float v1 = fmaxf(a.y * sg1[o+1] + sb1[o+1], 0.f);
            u64 v0p = pack2(v0, v0);
            u64 v1p = pack2(v1, v1);
            #pragma unroll
            for (int s4 = 0; s4 < 8; s4++) {
                ulonglong2 wp0 = w2T2[o*8 + s4];
                fma2(sacc2[s4*2+0], v0p, wp0.x);
                fma2(sacc2[s4*2+1], v0p, wp0.y);
            }
            #pragma unroll
            for (int s4 = 0; s4 < 8; s4++) {
                ulonglong2 wp1 = w2T2[(o+1)*8 + s4];
                fma2(sacc2[s4*2+0], v1p, wp1.x);
                fma2(sacc2[s4*2+1], v1p, wp1.y);
            }
        }
        float* op = skip_out + (size_t)b * 32 * HW1 + p + px * 128;
        #pragma unroll
        for (int s = 0; s < 16; s++) {
            float2 a = unpack2(sacc2[s]);
            op[(size_t)(2*s+0) * HW1] = fmaxf(a.x * sg2[2*s+0] + sb2[2*s+0], 0.f);
            op[(size_t)(2*s+1) * HW1] = fmaxf(a.y * sg2[2*s+1] + sb2[2*s+1], 0.f);
        }
    }
}

// ---------------------------------------------------------------------------
// Kernel B1: depth head. 48-channel GEMM + softmax depth + geometry.
// ---------------------------------------------------------------------------
__global__ __launch_bounds__(128, 4)
void kB1(const float* __restrict__ stage5,
         const float* __restrict__ wd, const float* __restrict__ gd, const float* __restrict__ bd,
         const float* __restrict__ intr, const float* __restrict__ extr)
{
    __shared__ __align__(16) float ws[64*48];
    __shared__ float sgd[48], sbd[48];
    int tid = threadIdx.x;
    if (tid < 48) { sgd[tid] = gd[tid]; sbd[tid] = bd[tid]; }
    int b = blockIdx.x / 88;
    int p = (blockIdx.x - b * 88) * 128 + tid;
    const float* xin = stage5 + (size_t)b * 512 * N5 + p;

    u64 acc2[24];
    #pragma unroll
    for (int i = 0; i < 24; i++) acc2[i] = 0ull;

    for (int c0 = 0; c0 < 512; c0 += 64) {
        __syncthreads();
        for (int i = tid; i < 64*48; i += 128) {
            int o = i % 48; int c = i / 48;
            ws[c*48 + o] = wd[o*512 + c0 + c];
        }
        __syncthreads();
        const ulonglong2* ws2 = (const ulonglong2*)ws;
        for (int c = 0; c < 64; c++) {
            float xv = xin[(size_t)(c0 + c) * N5];
            u64 xv2 = pack2(xv, xv);
            #pragma unroll
            for (int q = 0; q < 12; q++) {
                ulonglong2 wp = ws2[c*12 + q];
                fma2(acc2[q*2+0], xv2, wp.x);
                fma2(acc2[q*2+1], xv2, wp.y);
            }
        }
    }

    float m = -1e30f;
    #pragma unroll
    for (int q = 0; q < 24; q++) {
        float2 a = unpack2(acc2[q]);
        int j = 2*q;
        m = fmaxf(m, fmaxf(10.f * (a.x * sgd[j] + sbd[j]),
                           10.f * (a.y * sgd[j+1] + sbd[j+1])));
    }
    const float lstep = 0.08711371545f;  // ln(60)/47
    float sum = 0.f, dsum = 0.f;
    #pragma unroll
    for (int q = 0; q < 24; q++) {
        float2 a = unpack2(acc2[q]);
        int j = 2*q;
        float l0 = 10.f * (a.x * sgd[j]   + sbd[j]);
        float l1 = 10.f * (a.y * sgd[j+1] + sbd[j+1]);
        float e0 = __expf(l0 - m);
        float e1 = __expf(l1 - m);
        sum  += e0 + e1;
        dsum += e0 * __expf((float)j * lstep) + e1 * __expf((float)(j+1) * lstep);
    }
    float depth = dsum / sum;
    depth = fminf(fmaxf(depth, 1.0f), 65.0f);

    const float* K = intr + b * 9;
    float a00=K[0],a01=K[1],a02=K[2],a10=K[3],a11=K[4],a12=K[5],a20=K[6],a21=K[7],a22=K[8];
    float det = a00*(a11*a22 - a12*a21) - a01*(a10*a22 - a12*a20) + a02*(a10*a21 - a11*a20);
    float id = 1.0f / det;
    float i00 = (a11*a22 - a12*a21) * id;
    float i01 = (a02*a21 - a01*a22) * id;
    float i02 = (a01*a12 - a02*a11) * id;
    float i10 = (a12*a20 - a10*a22) * id;
    float i11 = (a00*a22 - a02*a20) * id;
    float i12 = (a02*a10 - a00*a12) * id;
    float i20 = (a10*a21 - a11*a20) * id;
    float i21 = (a01*a20 - a00*a21) * id;
    float i22 = (a00*a11 - a01*a10) * id;

    float py = (float)(p / W5i);
    float px = (float)(p - (p / W5i) * W5i);
    float cx = depth * (i00*px + i01*py + i02);
    float cy = depth * (i10*px + i11*py + i12);
    float cz = depth * (i20*px + i21*py + i22);

    const float* T = extr + b * 16;
    float ex = T[0]*cx + T[1]*cy + T[2]*cz  + T[3];
    float ey = T[4]*cx + T[5]*cy + T[6]*cz  + T[7];
    float ez = T[8]*cx + T[9]*cy + T[10]*cz + T[11];

    bool ev = (ex >= -51.2f) & (ex < 51.2f) & (ey >= -51.2f) & (ey < 51.2f)
            & (ez >= -5.0f)  & (ez < 3.0f);
    int bx = (int)floorf(ex / 0.4f + 64.0f);
    int by = (int)floorf(ey / 0.4f + 64.0f);
    bool gv = (bx >= 0) & (bx < 128) & (by >= 0) & (by < 128);

    int idx = -1; float wf = 0.f;
    if (ev & gv) {
        idx = ((b * 128 + by) * 128 + bx) * BEVC;
        wf = __expf(-0.05f * fabsf(ez));
    }
    g_sidx[b * N5 + p] = idx;
    g_swf [b * N5 + p] = wf;
}

// ---------------------------------------------------------------------------
// Kernel B2: reduced-feature GEMM (64 out) + scatter-add, 2 pixels/thread.
// launch_bounds(128,3) to lift occupancy 8 -> 12 warps/SM.
// ---------------------------------------------------------------------------
__global__ __launch_bounds__(128, 3)
void kB2(const float* __restrict__ stage5,
         const float* __restrict__ w5, const float* __restrict__ g5, const float* __restrict__ b5)
{
    __shared__ __align__(16) float ws[64*64];   // [c][o]
    __shared__ float sg[64], sb[64];
    int tid = threadIdx.x;
    if (tid < 64) { sg[tid] = g5[tid]; sb[tid] = b5[tid]; }
    int b = blockIdx.x / 44;
    int p = (blockIdx.x - b * 44) * 256 + tid;
    const float* xin = stage5 + (size_t)b * 512 * N5 + p;

    u64 acc[2][32];
    #pragma unroll
    for (int q = 0; q < 32; q++) { acc[0][q] = 0ull; acc[1][q] = 0ull; }

    for (int c0 = 0; c0 < 512; c0 += 64) {
        __syncthreads();
        for (int i = tid; i < 64*64; i += 128) {
            int o = i & 63; int c = i >> 6;
            ws[c*64 + o] = w5[o*512 + c0 + c];
        }
        __syncthreads();
        const ulonglong2* ws2 = (const ulonglong2*)ws;
        for (int c = 0; c < 64; c++) {
            const float* xc = xin + (size_t)(c0 + c) * N5;
            u64 x0 = pack2(xc[0],   xc[0]);
            u64 x1 = pack2(xc[128], xc[128]);
            #pragma unroll
            for (int q = 0; q < 16; q++) {
                ulonglong2 wp = ws2[c*16 + q];
                fma2(acc[0][q*2+0], x0, wp.x);
                fma2(acc[0][q*2+1], x0, wp.y);
                fma2(acc[1][q*2+0], x1, wp.x);
                fma2(acc[1][q*2+1], x1, wp.y);
            }
        }
    }

    #pragma unroll
    for (int px = 0; px < 2; px++) {
        int pp = p + px * 128;
        int idx = g_sidx[b * N5 + pp];
        float wf = g_swf[b * N5 + pp];
        if (idx >= 0) {
            float* cell = g_bev + idx;
            #pragma unroll
            for (int q = 0; q < 32; q++) {
                float2 a = unpack2(acc[px][q]);
                float r0 = fmaxf(a.x * sg[2*q+0] + sb[2*q+0], 0.f) * wf;
                float r1 = fmaxf(a.y * sg[2*q+1] + sb[2*q+1], 0.f) * wf;
                atomicAdd(cell + 2*q+0, r0);
                atomicAdd(cell + 2*q+1, r1);
            }
        }
    }
}

// ---------------------------------------------------------------------------
// Kernel C v4: 3x3 conv (64->128) + BN + ReLU.
// 32x16 tile, 2 px/thread, 32 oc/block, input channels chunked 2x32 so
// smem = 78K tile + 8K double-buffered per-kk weights -> 2 blocks/SM.
// ---------------------------------------------------------------------------
__global__ __launch_bounds__(256, 2)
void kC(const float* __restrict__ g, const float* __restrict__ bb,
        float* __restrict__ out)
{
    extern __shared__ __align__(16) float sm[];
    float* sin_ = sm;               // [ic 32][cell 612]  (18 x 34 tile)
    float* wbuf = sm + 32*612;      // [2][32ic * 32oc]
    int tid = threadIdx.x;
    int tx = tid & 31, ty = tid >> 5;        // ty 0..7
    int x0 = blockIdx.x * 32, y0 = blockIdx.y * 16;
    int bz = blockIdx.z;                     // 0..47
    int b = bz >> 2;
    int oc0 = (bz & 3) * 32;

    const float4* bev4 = (const float4*)g_bev;

    // --- load input tile for ic chunk 0 ---
    for (int i = tid; i < 612*8; i += 256) {
        int icg = i & 7;                 // float4 group 0..7 (chunk 0)
        int cell = i >> 3;
        int iy = cell / 34, ix = cell - iy * 34;
        int gy = y0 + iy - 1, gx = x0 + ix - 1;
        float4 v = make_float4(0.f, 0.f, 0.f, 0.f);
        if (gy >= 0 && gy < 128 && gx >= 0 && gx < 128)
            v = bev4[((((size_t)b * 128 + gy) * 128 + gx) << 4) + icg];
        sin_[(icg*4+0)*612 + cell] = v.x;
        sin_[(icg*4+1)*612 + cell] = v.y;
        sin_[(icg*4+2)*612 + cell] = v.z;
        sin_[(icg*4+3)*612 + cell] = v.w;
    }
    // --- stage weights for (chunk 0, kk 0) into wbuf[0] ---
    for (int i = tid; i < 1024; i += 256) {
        int icl = i >> 5, oc = i & 31;
        wbuf[i] = g_wt[(0*64 + 0*32 + icl)*128 + oc0 + oc];
    }
    __syncthreads();

    u64 acc[2][16];
    #pragma unroll
    for (int q = 0; q < 16; q++) { acc[0][q] = 0ull; acc[1][q] = 0ull; }

    for (int s = 0; s < 18; s++) {
        int buf = s & 1;
        if (s < 17) {
            int sn = s + 1;
            int kkn = (sn >= 9) ? sn - 9 : sn;
            int chn = (sn >= 9) ? 1 : 0;
            float* wdst = wbuf + (buf ^ 1) * 1024;
            for (int i = tid; i < 1024; i += 256) {
                int icl = i >> 5, oc = i & 31;
                wdst[i] = g_wt[(kkn*64 + chn*32 + icl)*128 + oc0 + oc];
            }
        }
        int kk = (s >= 9) ? s - 9 : s;
        int ky = kk / 3, kx = kk - ky*3;
        int base0 = (ty + ky) * 34 + tx + kx;
        int base1 = base0 + 8 * 34;
        const ulonglong2* wb = (const ulonglong2*)(wbuf + buf * 1024);
        #pragma unroll 4
        for (int ic = 0; ic < 32; ic++) {
            float xv0 = sin_[ic * 612 + base0];
            float xv1 = sin_[ic * 612 + base1];
            u64 x0p = pack2(xv0, xv0);
            u64 x1p = pack2(xv1, xv1);
            const ulonglong2* wrow = wb + ic*8;
            #pragma unroll
            for (int q = 0; q < 8; q++) {
                ulonglong2 wv = wrow[q];
                fma2(acc[0][2*q+0], x0p, wv.x);
                fma2(acc[0][2*q+1], x0p, wv.y);
                fma2(acc[1][2*q+0], x1p, wv.x);
                fma2(acc[1][2*q+1], x1p, wv.y);
            }
        }
        __syncthreads();
        if (s == 8) {
            // reload input tile for ic chunk 1 (all warps done with chunk 0)
            for (int i = tid; i < 612*8; i += 256) {
                int icg = (i & 7) + 8;          // float4 group 8..15 (chunk 1)
                int cell = i >> 3;
                int iy = cell / 34, ix = cell - iy * 34;
                int gy = y0 + iy - 1, gx = x0 + ix - 1;
                float4 v = make_float4(0.f, 0.f, 0.f, 0.f);
                if (gy >= 0 && gy < 128 && gx >= 0 && gx < 128)
                    v = bev4[((((size_t)b * 128 + gy) * 128 + gx) << 4) + icg];
                int icl = i & 7;
                sin_[(icl*4+0)*612 + cell] = v.x;
                sin_[(icl*4+1)*612 + cell] = v.y;
                sin_[(icl*4+2)*612 + cell] = v.z;
                sin_[(icl*4+3)*612 + cell] = v.w;
            }
            __syncthreads();
        }
    }

    #pragma unroll
    for (int px = 0; px < 2; px++) {
        float* op = out + (((size_t)b * 128 + oc0) * 128 + (y0 + ty + px*8)) * 128 + (x0 + tx);
        #pragma unroll
        for (int q = 0; q < 16; q++) {
            float2 a = unpack2(acc[px][q]);
            int o = 2*q;
            op[(size_t)(o+0) * 16384] = fmaxf(a.x * g[oc0 + o]     + bb[oc0 + o],     0.f);
            op[(size_t)(o+1) * 16384] = fmaxf(a.y * g[oc0 + o + 1] + bb[oc0 + o + 1], 0.f);
        }
    }
}

// ---------------------------------------------------------------------------
extern "C" void kernel_launch(void* const* d_in, const int* in_sizes, int n_in,
                              void* d_out, int out_size)
{
    const float* stage1 = (const float*)d_in[0];
    const float* stage5 = (const float*)d_in[1];
    const float* intr   = (const float*)d_in[2];
    const float* extr   = (const float*)d_in[3];
    const float* red1_w = (const float*)d_in[4];
    const float* red1_g = (const float*)d_in[5];
    const float* red1_b = (const float*)d_in[6];
    const float* skip_w = (const float*)d_in[7];
    const float* skip_g = (const float*)d_in[8];
    const float* skip_b = (const float*)d_in[9];
    const float* red5_w = (const float*)d_in[10];
    const float* red5_g = (const float*)d_in[11];
    const float* red5_b = (const float*)d_in[12];
    const float* dep5_w = (const float*)d_in[13];
    const float* dep5_g = (const float*)d_in[14];
    const float* dep5_b = (const float*)d_in[15];
    const float* main_w = (const float*)d_in[16];
    const float* main_g = (const float*)d_in[17];
    const float* main_b = (const float*)d_in[18];

    float* out_main = (float*)d_out;
    float* out_skip = (float*)d_out + OUT_MAIN;

    // side stream + events (created once; creation is not a captured op)
    static cudaStream_t s1 = nullptr;
    static cudaEvent_t eFork = nullptr, eJoin = nullptr;
    if (!s1) {
        cudaStreamCreateWithFlags(&s1, cudaStreamNonBlocking);
        cudaEventCreateWithFlags(&eFork, cudaEventDisableTiming);
        cudaEventCreateWithFlags(&eJoin, cudaEventDisableTiming);
    }

    // zero BEV scratch (critical path start)
    void* bevPtr = nullptr;
    cudaGetSymbolAddress(&bevPtr, g_bev);
    cudaMemsetAsync(bevPtr, 0, sizeof(float) * (size_t)Bn * 128 * 128 * BEVC);

    // fork: skip path runs concurrently on s1
    cudaEventRecord(eFork, 0);
    cudaStreamWaitEvent(s1, eFork, 0);
    kA<<<(Bn * HW1) / 256, 128, 0, s1>>>(stage1, red1_w, red1_g, red1_b,
                                         skip_w, skip_g, skip_b, out_skip);
    cudaEventRecord(eJoin, s1);

    // critical path on capture stream
    kWt<<<(9*64*128 + 255)/256, 256>>>(main_w);
    kB1<<<Bn * 88, 128>>>(stage5, dep5_w, dep5_g, dep5_b, intr, extr);
    kB2<<<Bn * 44, 128>>>(stage5, red5_w, red5_g, red5_b);

    // join before kC
    cudaStreamWaitEvent(0, eJoin, 0);

    // BEV conv v4: 2 blocks/SM
    int smem = (32*612 + 2*1024) * sizeof(float);   // 86528
    cudaFuncSetAttribute(kC, cudaFuncAttributeMaxDynamicSharedMemorySize, smem);
    dim3 gridC(4, 8, Bn * 4);
    kC<<<gridC, 256, smem>>>(main_g, main_b, out_main);
}

// round 11
// speedup vs baseline: 1.1414x; 1.0785x over previous
#include <cuda_runtime.h>
#include <math.h>

#define Bn 12
#define HW1 45056           // 128*352
#define N5 11264            // 64*176
#define W5i 176
#define BEVC 64
#define OUT_MAIN (12*128*128*128)   // 25165824

typedef unsigned long long u64;

// packed f32x2 helpers (sm_103a)
__device__ __forceinline__ u64 pack2(float lo, float hi) {
    u64 r; asm("mov.b64 %0, {%1, %2};" : "=l"(r) : "f"(lo), "f"(hi)); return r;
}
__device__ __forceinline__ void fma2(u64 &d, u64 a, u64 b) {
    asm("fma.rn.f32x2 %0, %1, %2, %0;" : "+l"(d) : "l"(a), "l"(b));
}
__device__ __forceinline__ float2 unpack2(u64 v) {
    float2 r; asm("mov.b64 {%0, %1}, %2;" : "=f"(r.x), "=f"(r.y) : "l"(v)); return r;
}

// BEV scratch, channels-last: [B][128][128][64]
__device__ float g_bev[Bn * 128 * 128 * BEVC];
__device__ int   g_sidx[Bn * N5];
__device__ float g_swf [Bn * N5];

// ---------------------------------------------------------------------------
// Kernel A: fused skip path, 2 pixels per thread.  (proven R3 version)
// ---------------------------------------------------------------------------
__global__ __launch_bounds__(128, 2)
void kA(const float* __restrict__ stage1,
        const float* __restrict__ w1, const float* __restrict__ g1, const float* __restrict__ b1,
        const float* __restrict__ w2, const float* __restrict__ g2, const float* __restrict__ b2,
        float* __restrict__ skip_out)
{
    __shared__ __align__(16) float w1T[64*64];   // [c][o]
    __shared__ __align__(16) float w2T[64*32];   // [o][s]
    __shared__ float sg1[64], sb1[64], sg2[32], sb2[32];
    int tid = threadIdx.x;
    for (int i = tid; i < 64*64; i += 128) { int o = i & 63, c = i >> 6; w1T[c*64+o] = w1[o*64+c]; }
    for (int i = tid; i < 64*32; i += 128) { int s = i & 31, o = i >> 5; w2T[o*32+s] = w2[s*64+o]; }
    if (tid < 64) { sg1[tid] = g1[tid]; sb1[tid] = b1[tid]; }
    if (tid < 32) { sg2[tid] = g2[tid]; sb2[tid] = b2[tid]; }
    __syncthreads();

    int gid = blockIdx.x * 256 + tid;
    int b = gid / HW1;
    int p = gid - b * HW1;
    const float* xin = stage1 + (size_t)b * 64 * HW1 + p;

    u64 acc[2][32];
    #pragma unroll
    for (int q = 0; q < 32; q++) { acc[0][q] = 0ull; acc[1][q] = 0ull; }

    const ulonglong2* w1T2 = (const ulonglong2*)w1T;
    for (int c = 0; c < 64; c++) {
        const float* xc = xin + (size_t)c * HW1;
        u64 x0 = pack2(xc[0],   xc[0]);
        u64 x1 = pack2(xc[128], xc[128]);
        #pragma unroll
        for (int q = 0; q < 16; q++) {
            ulonglong2 wp = w1T2[c*16 + q];
            fma2(acc[0][q*2+0], x0, wp.x);
            fma2(acc[0][q*2+1], x0, wp.y);
            fma2(acc[1][q*2+0], x1, wp.x);
            fma2(acc[1][q*2+1], x1, wp.y);
        }
    }

    const ulonglong2* w2T2 = (const ulonglong2*)w2T;
    #pragma unroll
    for (int px = 0; px < 2; px++) {
        u64 sacc2[16];
        #pragma unroll
        for (int s = 0; s < 16; s++) sacc2[s] = 0ull;
        #pragma unroll
        for (int q = 0; q < 32; q++) {
            float2 a = unpack2(acc[px][q]);
            int o = 2*q;
            float v0 = fmaxf(a.x * sg1[o]   + sb1[o],   0.f);
            float v1 = fmaxf(a.y * sg1[o+1] + sb1[o+1], 0.f);
            u64 v0p = pack2(v0, v0);
            u64 v1p = pack2(v1, v1);
            #pragma unroll
            for (int s4 = 0; s4 < 8; s4++) {
                ulonglong2 wp0 = w2T2[o*8 + s4];
                fma2(sacc2[s4*2+0], v0p, wp0.x);
                fma2(sacc2[s4*2+1], v0p, wp0.y);
            }
            #pragma unroll
            for (int s4 = 0; s4 < 8; s4++) {
                ulonglong2 wp1 = w2T2[(o+1)*8 + s4];
                fma2(sacc2[s4*2+0], v1p, wp1.x);
                fma2(sacc2[s4*2+1], v1p, wp1.y);
            }
        }
        float* op = skip_out + (size_t)b * 32 * HW1 + p + px * 128;
        #pragma unroll
        for (int s = 0; s < 16; s++) {
            float2 a = unpack2(sacc2[s]);
            op[(size_t)(2*s+0) * HW1] = fmaxf(a.x * sg2[2*s+0] + sb2[2*s+0], 0.f);
            op[(size_t)(2*s+1) * HW1] = fmaxf(a.y * sg2[2*s+1] + sb2[2*s+1], 0.f);
        }
    }
}

// ---------------------------------------------------------------------------
// Kernel B1: depth head. 48-channel GEMM + softmax depth + geometry.
// ---------------------------------------------------------------------------
__global__ __launch_bounds__(128, 4)
void kB1(const float* __restrict__ stage5,
         const float* __restrict__ wd, const float* __restrict__ gd, const float* __restrict__ bd,
         const float* __restrict__ intr, const float* __restrict__ extr)
{
    __shared__ __align__(16) float ws[64*48];
    __shared__ float sgd[48], sbd[48];
    int tid = threadIdx.x;
    if (tid < 48) { sgd[tid] = gd[tid]; sbd[tid] = bd[tid]; }
    int b = blockIdx.x / 88;
    int p = (blockIdx.x - b * 88) * 128 + tid;
    const float* xin = stage5 + (size_t)b * 512 * N5 + p;

    u64 acc2[24];
    #pragma unroll
    for (int i = 0; i < 24; i++) acc2[i] = 0ull;

    for (int c0 = 0; c0 < 512; c0 += 64) {
        __syncthreads();
        for (int i = tid; i < 64*48; i += 128) {
            int o = i % 48; int c = i / 48;
            ws[c*48 + o] = wd[o*512 + c0 + c];
        }
        __syncthreads();
        const ulonglong2* ws2 = (const ulonglong2*)ws;
        for (int c = 0; c < 64; c++) {
            float xv = xin[(size_t)(c0 + c) * N5];
            u64 xv2 = pack2(xv, xv);
            #pragma unroll
            for (int q = 0; q < 12; q++) {
                ulonglong2 wp = ws2[c*12 + q];
                fma2(acc2[q*2+0], xv2, wp.x);
                fma2(acc2[q*2+1], xv2, wp.y);
            }
        }
    }

    float m = -1e30f;
    #pragma unroll
    for (int q = 0; q < 24; q++) {
        float2 a = unpack2(acc2[q]);
        int j = 2*q;
        m = fmaxf(m, fmaxf(10.f * (a.x * sgd[j] + sbd[j]),
                           10.f * (a.y * sgd[j+1] + sbd[j+1])));
    }
    const float lstep = 0.08711371545f;  // ln(60)/47
    float sum = 0.f, dsum = 0.f;
    #pragma unroll
    for (int q = 0; q < 24; q++) {
        float2 a = unpack2(acc2[q]);
        int j = 2*q;
        float l0 = 10.f * (a.x * sgd[j]   + sbd[j]);
        float l1 = 10.f * (a.y * sgd[j+1] + sbd[j+1]);
        float e0 = __expf(l0 - m);
        float e1 = __expf(l1 - m);
        sum  += e0 + e1;
        dsum += e0 * __expf((float)j * lstep) + e1 * __expf((float)(j+1) * lstep);
    }
    float depth = dsum / sum;
    depth = fminf(fmaxf(depth, 1.0f), 65.0f);

    const float* K = intr + b * 9;
    float a00=K[0],a01=K[1],a02=K[2],a10=K[3],a11=K[4],a12=K[5],a20=K[6],a21=K[7],a22=K[8];
    float det = a00*(a11*a22 - a12*a21) - a01*(a10*a22 - a12*a20) + a02*(a10*a21 - a11*a20);
    float id = 1.0f / det;
    float i00 = (a11*a22 - a12*a21) * id;
    float i01 = (a02*a21 - a01*a22) * id;
    float i02 = (a01*a12 - a02*a11) * id;
    float i10 = (a12*a20 - a10*a22) * id;
    float i11 = (a00*a22 - a02*a20) * id;
    float i12 = (a02*a10 - a00*a12) * id;
    float i20 = (a10*a21 - a11*a20) * id;
    float i21 = (a01*a20 - a00*a21) * id;
    float i22 = (a00*a11 - a01*a10) * id;

    float py = (float)(p / W5i);
    float px = (float)(p - (p / W5i) * W5i);
    float cx = depth * (i00*px + i01*py + i02);
    float cy = depth * (i10*px + i11*py + i12);
    float cz = depth * (i20*px + i21*py + i22);

    const float* T = extr + b * 16;
    float ex = T[0]*cx + T[1]*cy + T[2]*cz  + T[3];
    float ey = T[4]*cx + T[5]*cy + T[6]*cz  + T[7];
    float ez = T[8]*cx + T[9]*cy + T[10]*cz + T[11];

    bool ev = (ex >= -51.2f) & (ex < 51.2f) & (ey >= -51.2f) & (ey < 51.2f)
            & (ez >= -5.0f)  & (ez < 3.0f);
    int bx = (int)floorf(ex / 0.4f + 64.0f);
    int by = (int)floorf(ey / 0.4f + 64.0f);
    bool gv = (bx >= 0) & (bx < 128) & (by >= 0) & (by < 128);

    int idx = -1; float wf = 0.f;
    if (ev & gv) {
        idx = ((b * 128 + by) * 128 + bx) * BEVC;
        wf = __expf(-0.05f * fabsf(ez));
    }
    g_sidx[b * N5 + p] = idx;
    g_swf [b * N5 + p] = wf;
}

// ---------------------------------------------------------------------------
// Kernel B2: reduced-feature GEMM (64 out) + scatter-add, 2 pixels/thread.
// (proven R3 version — NO register cap)
// ---------------------------------------------------------------------------
__global__ __launch_bounds__(128, 2)
void kB2(const float* __restrict__ stage5,
         const float* __restrict__ w5, const float* __restrict__ g5, const float* __restrict__ b5)
{
    __shared__ __align__(16) float ws[64*64];   // [c][o]
    __shared__ float sg[64], sb[64];
    int tid = threadIdx.x;
    if (tid < 64) { sg[tid] = g5[tid]; sb[tid] = b5[tid]; }
    int b = blockIdx.x / 44;
    int p = (blockIdx.x - b * 44) * 256 + tid;
    const float* xin = stage5 + (size_t)b * 512 * N5 + p;

    u64 acc[2][32];
    #pragma unroll
    for (int q = 0; q < 32; q++) { acc[0][q] = 0ull; acc[1][q] = 0ull; }

    for (int c0 = 0; c0 < 512; c0 += 64) {
        __syncthreads();
        for (int i = tid; i < 64*64; i += 128) {
            int o = i & 63; int c = i >> 6;
            ws[c*64 + o] = w5[o*512 + c0 + c];
        }
        __syncthreads();
        const ulonglong2* ws2 = (const ulonglong2*)ws;
        for (int c = 0; c < 64; c++) {
            const float* xc = xin + (size_t)(c0 + c) * N5;
            u64 x0 = pack2(xc[0],   xc[0]);
            u64 x1 = pack2(xc[128], xc[128]);
            #pragma unroll
            for (int q = 0; q < 16; q++) {
                ulonglong2 wp = ws2[c*16 + q];
                fma2(acc[0][q*2+0], x0, wp.x);
                fma2(acc[0][q*2+1], x0, wp.y);
                fma2(acc[1][q*2+0], x1, wp.x);
                fma2(acc[1][q*2+1], x1, wp.y);
            }
        }
    }

    #pragma unroll
    for (int px = 0; px < 2; px++) {
        int pp = p + px * 128;
        int idx = g_sidx[b * N5 + pp];
        float wf = g_swf[b * N5 + pp];
        if (idx >= 0) {
            float* cell = g_bev + idx;
            #pragma unroll
            for (int q = 0; q < 32; q++) {
                float2 a = unpack2(acc[px][q]);
                float r0 = fmaxf(a.x * sg[2*q+0] + sb[2*q+0], 0.f) * wf;
                float r1 = fmaxf(a.y * sg[2*q+1] + sb[2*q+1], 0.f) * wf;
                atomicAdd(cell + 2*q+0, r0);
                atomicAdd(cell + 2*q+1, r1);
            }
        }
    }
}

// ---------------------------------------------------------------------------
// Kernel C (proven R3 v1): 3x3 conv (64->128) + BN + ReLU.
// 32x16 spatial tile, 2 px/thread, 32 oc/block, static weight tile in smem.
// ---------------------------------------------------------------------------
__global__ __launch_bounds__(256, 1)
void kC(const float* __restrict__ w, const float* __restrict__ g, const float* __restrict__ bb,
        float* __restrict__ out)
{
    extern __shared__ __align__(16) float sm[];
    float* sin_ = sm;               // [ic 64][cell 612]  (18 x 34 tile)
    float* wsh  = sm + 64*612;      // [(kk*64+ic)*32 + ocl]
    int tid = threadIdx.x;
    int tx = tid & 31, ty = tid >> 5;        // ty 0..7
    int x0 = blockIdx.x * 32, y0 = blockIdx.y * 16;
    int bz = blockIdx.z;
    int b = bz >> 2;
    int oc0 = (bz & 3) * 32;

    // weights -> shared
    for (int i = tid; i < 18432; i += 256) {
        int ocl = i & 31;
        int t = i >> 5;
        int ic = t & 63;
        int kk = t >> 6;
        wsh[i] = w[((oc0 + ocl) * 64 + ic) * 9 + kk];
    }
    // input tile (with halo, zero padded) -> shared
    const float4* bev4 = (const float4*)g_bev;
    for (int i = tid; i < 612*16; i += 256) {
        int icg = i & 15;
        int cell = i >> 4;
        int iy = cell / 34, ix = cell - iy * 34;
        int gy = y0 + iy - 1, gx = x0 + ix - 1;
        float4 v = make_float4(0.f, 0.f, 0.f, 0.f);
        if (gy >= 0 && gy < 128 && gx >= 0 && gx < 128)
            v = bev4[((((size_t)b * 128 + gy) * 128 + gx) << 4) + icg];
        sin_[(icg*4+0)*612 + cell] = v.x;
        sin_[(icg*4+1)*612 + cell] = v.y;
        sin_[(icg*4+2)*612 + cell] = v.z;
        sin_[(icg*4+3)*612 + cell] = v.w;
    }
    __syncthreads();

    u64 acc2[2][16];
    #pragma unroll
    for (int q = 0; q < 16; q++) { acc2[0][q] = 0ull; acc2[1][q] = 0ull; }
    const ulonglong2* wsh2 = (const ulonglong2*)wsh;   // 8 per (kk,ic)

    for (int ky = 0; ky < 3; ky++) {
        for (int kx = 0; kx < 3; kx++) {
            int base0 = (ty + ky) * 34 + tx + kx;
            int base1 = base0 + 8 * 34;
            int kk = ky * 3 + kx;
            #pragma unroll 4
            for (int ic = 0; ic < 64; ic++) {
                float xv0 = sin_[ic * 612 + base0];
                float xv1 = sin_[ic * 612 + base1];
                u64 x0p = pack2(xv0, xv0);
                u64 x1p = pack2(xv1, xv1);
                #pragma unroll
                for (int q = 0; q < 8; q++) {
                    ulonglong2 wv = wsh2[(kk*64 + ic)*8 + q];
                    fma2(acc2[0][q*2+0], x0p, wv.x);
                    fma2(acc2[0][q*2+1], x0p, wv.y);
                    fma2(acc2[1][q*2+0], x1p, wv.x);
                    fma2(acc2[1][q*2+1], x1p, wv.y);
                }
            }
        }
    }

    #pragma unroll
    for (int px = 0; px < 2; px++) {
        float* op = out + (((size_t)b * 128 + oc0) * 128 + (y0 + ty + px*8)) * 128 + (x0 + tx);
        #pragma unroll
        for (int q = 0; q < 16; q++) {
            float2 a = unpack2(acc2[px][q]);
            int o = 2*q;
            op[(size_t)(o+0) * 16384] = fmaxf(a.x * g[oc0 + o]     + bb[oc0 + o],     0.f);
            op[(size_t)(o+1) * 16384] = fmaxf(a.y * g[oc0 + o + 1] + bb[oc0 + o + 1], 0.f);
        }
    }
}

// ---------------------------------------------------------------------------
extern "C" void kernel_launch(void* const* d_in, const int* in_sizes, int n_in,
                              void* d_out, int out_size)
{
    const float* stage1 = (const float*)d_in[0];
    const float* stage5 = (const float*)d_in[1];
    const float* intr   = (const float*)d_in[2];
    const float* extr   = (const float*)d_in[3];
    const float* red1_w = (const float*)d_in[4];
    const float* red1_g = (const float*)d_in[5];
    const float* red1_b = (const float*)d_in[6];
    const float* skip_w = (const float*)d_in[7];
    const float* skip_g = (const float*)d_in[8];
    const float* skip_b = (const float*)d_in[9];
    const float* red5_w = (const float*)d_in[10];
    const float* red5_g = (const float*)d_in[11];
    const float* red5_b = (const float*)d_in[12];
    const float* dep5_w = (const float*)d_in[13];
    const float* dep5_g = (const float*)d_in[14];
    const float* dep5_b = (const float*)d_in[15];
    const float* main_w = (const float*)d_in[16];
    const float* main_g = (const float*)d_in[17];
    const float* main_b = (const float*)d_in[18];

    float* out_main = (float*)d_out;
    float* out_skip = (float*)d_out + OUT_MAIN;

    // side stream + events (created once; creation is not a captured op)
    static cudaStream_t s1 = nullptr;
    static cudaEvent_t eFork = nullptr, eJoin = nullptr;
    if (!s1) {
        cudaStreamCreateWithFlags(&s1, cudaStreamNonBlocking);
        cudaEventCreateWithFlags(&eFork, cudaEventDisableTiming);
        cudaEventCreateWithFlags(&eJoin, cudaEventDisableTiming);
    }

    // zero BEV scratch (critical path start)
    void* bevPtr = nullptr;
    cudaGetSymbolAddress(&bevPtr, g_bev);
    cudaMemsetAsync(bevPtr, 0, sizeof(float) * (size_t)Bn * 128 * 128 * BEVC);

    // fork: skip path runs concurrently on s1
    cudaEventRecord(eFork, 0);
    cudaStreamWaitEvent(s1, eFork, 0);
    kA<<<(Bn * HW1) / 256, 128, 0, s1>>>(stage1, red1_w, red1_g, red1_b,
                                         skip_w, skip_g, skip_b, out_skip);
    cudaEventRecord(eJoin, s1);

    // critical path on capture stream
    kB1<<<Bn * 88, 128>>>(stage5, dep5_w, dep5_g, dep5_b, intr, extr);
    kB2<<<Bn * 44, 128>>>(stage5, red5_w, red5_g, red5_b);

    // join before kC
    cudaStreamWaitEvent(0, eJoin, 0);

    // BEV conv (proven R3 v1)
    int smem = (64*612 + 18432) * sizeof(float);   // 230400
    cudaFuncSetAttribute(kC, cudaFuncAttributeMaxDynamicSharedMemorySize, smem);
    dim3 gridC(4, 8, Bn * 4);
    kC<<<gridC, 256, smem>>>(main_w, main_g, main_b, out_main);
}

// round 12
// speedup vs baseline: 1.2258x; 1.0739x over previous
#include <cuda_runtime.h>
#include <math.h>

#define Bn 12
#define HW1 45056           // 128*352
#define N5 11264            // 64*176
#define W5i 176
#define BEVC 64
#define OUT_MAIN (12*128*128*128)   // 25165824

typedef unsigned long long u64;

// packed f32x2 helpers (sm_103a)
__device__ __forceinline__ u64 pack2(float lo, float hi) {
    u64 r; asm("mov.b64 %0, {%1, %2};" : "=l"(r) : "f"(lo), "f"(hi)); return r;
}
__device__ __forceinline__ void fma2(u64 &d, u64 a, u64 b) {
    asm("fma.rn.f32x2 %0, %1, %2, %0;" : "+l"(d) : "l"(a), "l"(b));
}
__device__ __forceinline__ float2 unpack2(u64 v) {
    float2 r; asm("mov.b64 {%0, %1}, %2;" : "=f"(r.x), "=f"(r.y) : "l"(v)); return r;
}

// BEV scratch, channels-last: [B][128][128][64]
__device__ float g_bev[Bn * 128 * 128 * BEVC];
__device__ int   g_sidx[Bn * N5];
__device__ float g_swf [Bn * N5];
// transposed conv weights: [kk 9][ic 64][oc 128]
__device__ float g_wt[9 * 64 * 128];

// ---------------------------------------------------------------------------
// kWt: transpose main conv weights into g_wt  (tiny)
// ---------------------------------------------------------------------------
__global__ void kWt(const float* __restrict__ w)
{
    int i = blockIdx.x * 256 + threadIdx.x;
    if (i < 9*64*128) {
        int oc = i & 127;
        int t  = i >> 7;
        int ic = t & 63;
        int kk = t >> 6;
        g_wt[i] = w[(oc*64 + ic)*9 + kk];
    }
}

// ---------------------------------------------------------------------------
// Kernel A: fused skip path, 2 pixels per thread.  (proven R3 version)
// ---------------------------------------------------------------------------
__global__ __launch_bounds__(128, 2)
void kA(const float* __restrict__ stage1,
        const float* __restrict__ w1, const float* __restrict__ g1, const float* __restrict__ b1,
        const float* __restrict__ w2, const float* __restrict__ g2, const float* __restrict__ b2,
        float* __restrict__ skip_out)
{
    __shared__ __align__(16) float w1T[64*64];   // [c][o]
    __shared__ __align__(16) float w2T[64*32];   // [o][s]
    __shared__ float sg1[64], sb1[64], sg2[32], sb2[32];
    int tid = threadIdx.x;
    for (int i = tid; i < 64*64; i += 128) { int o = i & 63, c = i >> 6; w1T[c*64+o] = w1[o*64+c]; }
    for (int i = tid; i < 64*32; i += 128) { int s = i & 31, o = i >> 5; w2T[o*32+s] = w2[s*64+o]; }
    if (tid < 64) { sg1[tid] = g1[tid]; sb1[tid] = b1[tid]; }
    if (tid < 32) { sg2[tid] = g2[tid]; sb2[tid] = b2[tid]; }
    __syncthreads();

    int gid = blockIdx.x * 256 + tid;
    int b = gid / HW1;
    int p = gid - b * HW1;
    const float* xin = stage1 + (size_t)b * 64 * HW1 + p;

    u64 acc[2][32];
    #pragma unroll
    for (int q = 0; q < 32; q++) { acc[0][q] = 0ull; acc[1][q] = 0ull; }

    const ulonglong2* w1T2 = (const ulonglong2*)w1T;
    for (int c = 0; c < 64; c++) {
        const float* xc = xin + (size_t)c * HW1;
        u64 x0 = pack2(xc[0],   xc[0]);
        u64 x1 = pack2(xc[128], xc[128]);
        #pragma unroll
        for (int q = 0; q < 16; q++) {
            ulonglong2 wp = w1T2[c*16 + q];
            fma2(acc[0][q*2+0], x0, wp.x);
            fma2(acc[0][q*2+1], x0, wp.y);
            fma2(acc[1][q*2+0], x1, wp.x);
            fma2(acc[1][q*2+1], x1, wp.y);
        }
    }

    const ulonglong2* w2T2 = (const ulonglong2*)w2T;
    #pragma unroll
    for (int px = 0; px < 2; px++) {
        u64 sacc2[16];
        #pragma unroll
        for (int s = 0; s < 16; s++) sacc2[s] = 0ull;
        #pragma unroll
        for (int q = 0; q < 32; q++) {
            float2 a = unpack2(acc[px][q]);
            int o = 2*q;
            float v0 = fmaxf(a.x * sg1[o]   + sb1[o],   0.f);
            float v1 = fmaxf(a.y * sg1[o+1] + sb1[o+1], 0.f);
            u64 v0p = pack2(v0, v0);
            u64 v1p = pack2(v1, v1);
            #pragma unroll
            for (int s4 = 0; s4 < 8; s4++) {
                ulonglong2 wp0 = w2T2[o*8 + s4];
                fma2(sacc2[s4*2+0], v0p, wp0.x);
                fma2(sacc2[s4*2+1], v0p, wp0.y);
            }
            #pragma unroll
            for (int s4 = 0; s4 < 8; s4++) {
                ulonglong2 wp1 = w2T2[(o+1)*8 + s4];
                fma2(sacc2[s4*2+0], v1p, wp1.x);
                fma2(sacc2[s4*2+1], v1p, wp1.y);
            }
        }
        float* op = skip_out + (size_t)b * 32 * HW1 + p + px * 128;
        #pragma unroll
        for (int s = 0; s < 16; s++) {
            float2 a = unpack2(sacc2[s]);
            op[(size_t)(2*s+0) * HW1] = fmaxf(a.x * sg2[2*s+0] + sb2[2*s+0], 0.f);
            op[(size_t)(2*s+1) * HW1] = fmaxf(a.y * sg2[2*s+1] + sb2[2*s+1], 0.f);
        }
    }
}

// ---------------------------------------------------------------------------
// Kernel B1: depth head. 48-channel GEMM + softmax depth + geometry.
// ---------------------------------------------------------------------------
__global__ __launch_bounds__(128, 4)
void kB1(const float* __restrict__ stage5,
         const float* __restrict__ wd, const float* __restrict__ gd, const float* __restrict__ bd,
         const float* __restrict__ intr, const float* __restrict__ extr)
{
    __shared__ __align__(16) float ws[64*48];
    __shared__ float sgd[48], sbd[48];
    int tid = threadIdx.x;
    if (tid < 48) { sgd[tid] = gd[tid]; sbd[tid] = bd[tid]; }
    int b = blockIdx.x / 88;
    int p = (blockIdx.x - b * 88) * 128 + tid;
    const float* xin = stage5 + (size_t)b * 512 * N5 + p;

    u64 acc2[24];
    #pragma unroll
    for (int i = 0; i < 24; i++) acc2[i] = 0ull;

    for (int c0 = 0; c0 < 512; c0 += 64) {
        __syncthreads();
        for (int i = tid; i < 64*48; i += 128) {
            int o = i % 48; int c = i / 48;
            ws[c*48 + o] = wd[o*512 + c0 + c];
        }
        __syncthreads();
        const ulonglong2* ws2 = (const ulonglong2*)ws;
        for (int c = 0; c < 64; c++) {
            float xv = xin[(size_t)(c0 + c) * N5];
            u64 xv2 = pack2(xv, xv);
            #pragma unroll
            for (int q = 0; q < 12; q++) {
                ulonglong2 wp = ws2[c*12 + q];
                fma2(acc2[q*2+0], xv2, wp.x);
                fma2(acc2[q*2+1], xv2, wp.y);
            }
        }
    }

    float m = -1e30f;
    #pragma unroll
    for (int q = 0; q < 24; q++) {
        float2 a = unpack2(acc2[q]);
        int j = 2*q;
        m = fmaxf(m, fmaxf(10.f * (a.x * sgd[j] + sbd[j]),
                           10.f * (a.y * sgd[j+1] + sbd[j+1])));
    }
    const float lstep = 0.08711371545f;  // ln(60)/47
    float sum = 0.f, dsum = 0.f;
    #pragma unroll
    for (int q = 0; q < 24; q++) {
        float2 a = unpack2(acc2[q]);
        int j = 2*q;
        float l0 = 10.f * (a.x * sgd[j]   + sbd[j]);
        float l1 = 10.f * (a.y * sgd[j+1] + sbd[j+1]);
        float e0 = __expf(l0 - m);
        float e1 = __expf(l1 - m);
        sum  += e0 + e1;
        dsum += e0 * __expf((float)j * lstep) + e1 * __expf((float)(j+1) * lstep);
    }
    float depth = dsum / sum;
    depth = fminf(fmaxf(depth, 1.0f), 65.0f);

    const float* K = intr + b * 9;
    float a00=K[0],a01=K[1],a02=K[2],a10=K[3],a11=K[4],a12=K[5],a20=K[6],a21=K[7],a22=K[8];
    float det = a00*(a11*a22 - a12*a21) - a01*(a10*a22 - a12*a20) + a02*(a10*a21 - a11*a20);
    float id = 1.0f / det;
    float i00 = (a11*a22 - a12*a21) * id;
    float i01 = (a02*a21 - a01*a22) * id;
    float i02 = (a01*a12 - a02*a11) * id;
    float i10 = (a12*a20 - a10*a22) * id;
    float i11 = (a00*a22 - a02*a20) * id;
    float i12 = (a02*a10 - a00*a12) * id;
    float i20 = (a10*a21 - a11*a20) * id;
    float i21 = (a01*a20 - a00*a21) * id;
    float i22 = (a00*a11 - a01*a10) * id;

    float py = (float)(p / W5i);
    float px = (float)(p - (p / W5i) * W5i);
    float cx = depth * (i00*px + i01*py + i02);
    float cy = depth * (i10*px + i11*py + i12);
    float cz = depth * (i20*px + i21*py + i22);

    const float* T = extr + b * 16;
    float ex = T[0]*cx + T[1]*cy + T[2]*cz  + T[3];
    float ey = T[4]*cx + T[5]*cy + T[6]*cz  + T[7];
    float ez = T[8]*cx + T[9]*cy + T[10]*cz + T[11];

    bool ev = (ex >= -51.2f) & (ex < 51.2f) & (ey >= -51.2f) & (ey < 51.2f)
            & (ez >= -5.0f)  & (ez < 3.0f);
    int bx = (int)floorf(ex / 0.4f + 64.0f);
    int by = (int)floorf(ey / 0.4f + 64.0f);
    bool gv = (bx >= 0) & (bx < 128) & (by >= 0) & (by < 128);

    int idx = -1; float wf = 0.f;
    if (ev & gv) {
        idx = ((b * 128 + by) * 128 + bx) * BEVC;
        wf = __expf(-0.05f * fabsf(ez));
    }
    g_sidx[b * N5 + p] = idx;
    g_swf [b * N5 + p] = wf;
}

// ---------------------------------------------------------------------------
// Kernel B2: reduced-feature GEMM (64 out) + scatter-add, 2 pixels/thread.
// Software pipeline: x prefetched 2 channels ahead to cover L2 latency.
// ---------------------------------------------------------------------------
__global__ __launch_bounds__(128, 2)
void kB2(const float* __restrict__ stage5,
         const float* __restrict__ w5, const float* __restrict__ g5, const float* __restrict__ b5)
{
    __shared__ __align__(16) float ws[64*64];   // [c][o]
    __shared__ float sg[64], sb[64];
    int tid = threadIdx.x;
    if (tid < 64) { sg[tid] = g5[tid]; sb[tid] = b5[tid]; }
    int b = blockIdx.x / 44;
    int p = (blockIdx.x - b * 44) * 256 + tid;
    const float* xin = stage5 + (size_t)b * 512 * N5 + p;

    u64 acc[2][32];
    #pragma unroll
    for (int q = 0; q < 32; q++) { acc[0][q] = 0ull; acc[1][q] = 0ull; }

    for (int c0 = 0; c0 < 512; c0 += 64) {
        __syncthreads();
        for (int i = tid; i < 64*64; i += 128) {
            int o = i & 63; int c = i >> 6;
            ws[c*64 + o] = w5[o*512 + c0 + c];
        }
        __syncthreads();
        const ulonglong2* ws2 = (const ulonglong2*)ws;
        // prefetch pipeline (depth 2)
        float p0a = xin[(size_t)(c0+0) * N5];
        float p0b = xin[(size_t)(c0+0) * N5 + 128];
        float p1a = xin[(size_t)(c0+1) * N5];
        float p1b = xin[(size_t)(c0+1) * N5 + 128];
        for (int c = 0; c < 64; c++) {
            int gcn = c0 + c + 2; if (gcn > 511) gcn = 511;
            float na = xin[(size_t)gcn * N5];
            float nb = xin[(size_t)gcn * N5 + 128];
            u64 x0 = pack2(p0a, p0a);
            u64 x1 = pack2(p0b, p0b);
            #pragma unroll
            for (int q = 0; q < 16; q++) {
                ulonglong2 wp = ws2[c*16 + q];
                fma2(acc[0][q*2+0], x0, wp.x);
                fma2(acc[0][q*2+1], x0, wp.y);
                fma2(acc[1][q*2+0], x1, wp.x);
                fma2(acc[1][q*2+1], x1, wp.y);
            }
            p0a = p1a; p0b = p1b; p1a = na; p1b = nb;
        }
    }

    #pragma unroll
    for (int px = 0; px < 2; px++) {
        int pp = p + px * 128;
        int idx = g_sidx[b * N5 + pp];
        float wf = g_swf[b * N5 + pp];
        if (idx >= 0) {
            float* cell = g_bev + idx;
            #pragma unroll
            for (int q = 0; q < 32; q++) {
                float2 a = unpack2(acc[px][q]);
                float r0 = fmaxf(a.x * sg[2*q+0] + sb[2*q+0], 0.f) * wf;
                float r1 = fmaxf(a.y * sg[2*q+1] + sb[2*q+1], 0.f) * wf;
                atomicAdd(cell + 2*q+0, r0);
                atomicAdd(cell + 2*q+1, r1);
            }
        }
    }
}

// ---------------------------------------------------------------------------
// Kernel C v4: 3x3 conv (64->128) + BN + ReLU.
// 32x16 tile, 2 px/thread, 32 oc/block, input channels chunked 2x32 so
// smem = 78K tile + 8K double-buffered per-kk weights -> 2 blocks/SM.
// ---------------------------------------------------------------------------
__global__ __launch_bounds__(256, 2)
void kC(const float* __restrict__ g, const float* __restrict__ bb,
        float* __restrict__ out)
{
    extern __shared__ __align__(16) float sm[];
    float* sin_ = sm;               // [ic 32][cell 612]  (18 x 34 tile)
    float* wbuf = sm + 32*612;      // [2][32ic * 32oc]
    int tid = threadIdx.x;
    int tx = tid & 31, ty = tid >> 5;        // ty 0..7
    int x0 = blockIdx.x * 32, y0 = blockIdx.y * 16;
    int bz = blockIdx.z;                     // 0..47
    int b = bz >> 2;
    int oc0 = (bz & 3) * 32;

    const float4* bev4 = (const float4*)g_bev;

    // --- load input tile for ic chunk 0 ---
    for (int i = tid; i < 612*8; i += 256) {
        int icg = i & 7;                 // float4 group 0..7 (chunk 0)
        int cell = i >> 3;
        int iy = cell / 34, ix = cell - iy * 34;
        int gy = y0 + iy - 1, gx = x0 + ix - 1;
        float4 v = make_float4(0.f, 0.f, 0.f, 0.f);
        if (gy >= 0 && gy < 128 && gx >= 0 && gx < 128)
            v = bev4[((((size_t)b * 128 + gy) * 128 + gx) << 4) + icg];
        sin_[(icg*4+0)*612 + cell] = v.x;
        sin_[(icg*4+1)*612 + cell] = v.y;
        sin_[(icg*4+2)*612 + cell] = v.z;
        sin_[(icg*4+3)*612 + cell] = v.w;
    }
    // --- stage weights for (chunk 0, kk 0) into wbuf[0] ---
    for (int i = tid; i < 1024; i += 256) {
        int icl = i >> 5, oc = i & 31;
        wbuf[i] = g_wt[(0*64 + 0*32 + icl)*128 + oc0 + oc];
    }
    __syncthreads();

    u64 acc[2][16];
    #pragma unroll
    for (int q = 0; q < 16; q++) { acc[0][q] = 0ull; acc[1][q] = 0ull; }

    for (int s = 0; s < 18; s++) {
        int buf = s & 1;
        if (s < 17) {
            int sn = s + 1;
            int kkn = (sn >= 9) ? sn - 9 : sn;
            int chn = (sn >= 9) ? 1 : 0;
            float* wdst = wbuf + (buf ^ 1) * 1024;
            for (int i = tid; i < 1024; i += 256) {
                int icl = i >> 5, oc = i & 31;
                wdst[i] = g_wt[(kkn*64 + chn*32 + icl)*128 + oc0 + oc];
            }
        }
        int kk = (s >= 9) ? s - 9 : s;
        int ky = kk / 3, kx = kk - ky*3;
        int base0 = (ty + ky) * 34 + tx + kx;
        int base1 = base0 + 8 * 34;
        const ulonglong2* wb = (const ulonglong2*)(wbuf + buf * 1024);
        #pragma unroll 4
        for (int ic = 0; ic < 32; ic++) {
            float xv0 = sin_[ic * 612 + base0];
            float xv1 = sin_[ic * 612 + base1];
            u64 x0p = pack2(xv0, xv0);
            u64 x1p = pack2(xv1, xv1);
            const ulonglong2* wrow = wb + ic*8;
            #pragma unroll
            for (int q = 0; q < 8; q++) {
                ulonglong2 wv = wrow[q];
                fma2(acc[0][2*q+0], x0p, wv.x);
                fma2(acc[0][2*q+1], x0p, wv.y);
                fma2(acc[1][2*q+0], x1p, wv.x);
                fma2(acc[1][2*q+1], x1p, wv.y);
            }
        }
        __syncthreads();
        if (s == 8) {
            // reload input tile for ic chunk 1 (all warps done with chunk 0)
            for (int i = tid; i < 612*8; i += 256) {
                int icg = (i & 7) + 8;          // float4 group 8..15 (chunk 1)
                int cell = i >> 3;
                int iy = cell / 34, ix = cell - iy * 34;
                int gy = y0 + iy - 1, gx = x0 + ix - 1;
                float4 v = make_float4(0.f, 0.f, 0.f, 0.f);
                if (gy >= 0 && gy < 128 && gx >= 0 && gx < 128)
                    v = bev4[((((size_t)b * 128 + gy) * 128 + gx) << 4) + icg];
                int icl = i & 7;
                sin_[(icl*4+0)*612 + cell] = v.x;
                sin_[(icl*4+1)*612 + cell] = v.y;
                sin_[(icl*4+2)*612 + cell] = v.z;
                sin_[(icl*4+3)*612 + cell] = v.w;
            }
            __syncthreads();
        }
    }

    #pragma unroll
    for (int px = 0; px < 2; px++) {
        float* op = out + (((size_t)b * 128 + oc0) * 128 + (y0 + ty + px*8)) * 128 + (x0 + tx);
        #pragma unroll
        for (int q = 0; q < 16; q++) {
            float2 a = unpack2(acc[px][q]);
            int o = 2*q;
            op[(size_t)(o+0) * 16384] = fmaxf(a.x * g[oc0 + o]     + bb[oc0 + o],     0.f);
            op[(size_t)(o+1) * 16384] = fmaxf(a.y * g[oc0 + o + 1] + bb[oc0 + o + 1], 0.f);
        }
    }
}

// ---------------------------------------------------------------------------
extern "C" void kernel_launch(void* const* d_in, const int* in_sizes, int n_in,
                              void* d_out, int out_size)
{
    const float* stage1 = (const float*)d_in[0];
    const float* stage5 = (const float*)d_in[1];
    const float* intr   = (const float*)d_in[2];
    const float* extr   = (const float*)d_in[3];
    const float* red1_w = (const float*)d_in[4];
    const float* red1_g = (const float*)d_in[5];
    const float* red1_b = (const float*)d_in[6];
    const float* skip_w = (const float*)d_in[7];
    const float* skip_g = (const float*)d_in[8];
    const float* skip_b = (const float*)d_in[9];
    const float* red5_w = (const float*)d_in[10];
    const float* red5_g = (const float*)d_in[11];
    const float* red5_b = (const float*)d_in[12];
    const float* dep5_w = (const float*)d_in[13];
    const float* dep5_g = (const float*)d_in[14];
    const float* dep5_b = (const float*)d_in[15];
    const float* main_w = (const float*)d_in[16];
    const float* main_g = (const float*)d_in[17];
    const float* main_b = (const float*)d_in[18];

    float* out_main = (float*)d_out;
    float* out_skip = (float*)d_out + OUT_MAIN;

    // side stream + events (created once; creation is not a captured op)
    static cudaStream_t s1 = nullptr;
    static cudaEvent_t eFork = nullptr, eJoin = nullptr;
    if (!s1) {
        cudaStreamCreateWithFlags(&s1, cudaStreamNonBlocking);
        cudaEventCreateWithFlags(&eFork, cudaEventDisableTiming);
        cudaEventCreateWithFlags(&eJoin, cudaEventDisableTiming);
    }

    // zero BEV scratch (critical path start)
    void* bevPtr = nullptr;
    cudaGetSymbolAddress(&bevPtr, g_bev);
    cudaMemsetAsync(bevPtr, 0, sizeof(float) * (size_t)Bn * 128 * 128 * BEVC);

    // fork: skip path runs concurrently on s1
    cudaEventRecord(eFork, 0);
    cudaStreamWaitEvent(s1, eFork, 0);
    kA<<<(Bn * HW1) / 256, 128, 0, s1>>>(stage1, red1_w, red1_g, red1_b,
                                         skip_w, skip_g, skip_b, out_skip);
    cudaEventRecord(eJoin, s1);

    // critical path on capture stream
    kWt<<<(9*64*128 + 255)/256, 256>>>(main_w);
    kB1<<<Bn * 88, 128>>>(stage5, dep5_w, dep5_g, dep5_b, intr, extr);
    kB2<<<Bn * 44, 128>>>(stage5, red5_w, red5_g, red5_b);

    // join before kC
    cudaStreamWaitEvent(0, eJoin, 0);

    // BEV conv v4: 2 blocks/SM
    int smem = (32*612 + 2*1024) * sizeof(float);   // 86528
    cudaFuncSetAttribute(kC, cudaFuncAttributeMaxDynamicSharedMemorySize, smem);
    dim3 gridC(4, 8, Bn * 4);
    kC<<<gridC, 256, smem>>>(main_g, main_b, out_main);
}

// round 13
// speedup vs baseline: 1.2991x; 1.0597x over previous
#include <cuda_runtime.h>
#include <math.h>

#define Bn 12
#define HW1 45056           // 128*352
#define N5 11264            // 64*176
#define W5i 176
#define BEVC 64
#define OUT_MAIN (12*128*128*128)   // 25165824

typedef unsigned long long u64;

// packed f32x2 helpers (sm_103a)
__device__ __forceinline__ u64 pack2(float lo, float hi) {
    u64 r; asm("mov.b64 %0, {%1, %2};" : "=l"(r) : "f"(lo), "f"(hi)); return r;
}
__device__ __forceinline__ void fma2(u64 &d, u64 a, u64 b) {
    asm("fma.rn.f32x2 %0, %1, %2, %0;" : "+l"(d) : "l"(a), "l"(b));
}
__device__ __forceinline__ float2 unpack2(u64 v) {
    float2 r; asm("mov.b64 {%0, %1}, %2;" : "=f"(r.x), "=f"(r.y) : "l"(v)); return r;
}

// BEV scratch, channels-last: [B][128][128][64]
__device__ float g_bev[Bn * 128 * 128 * BEVC];
__device__ int   g_sidx[Bn * N5];
__device__ float g_swf [Bn * N5];
// transposed conv weights: [kk 9][ic 64][oc 128]
__device__ float g_wt[9 * 64 * 128];

// ---------------------------------------------------------------------------
// kWt: transpose main conv weights into g_wt  (tiny)
// ---------------------------------------------------------------------------
__global__ void kWt(const float* __restrict__ w)
{
    int i = blockIdx.x * 256 + threadIdx.x;
    if (i < 9*64*128) {
        int oc = i & 127;
        int t  = i >> 7;
        int ic = t & 63;
        int kk = t >> 6;
        g_wt[i] = w[(oc*64 + ic)*9 + kk];
    }
}

// ---------------------------------------------------------------------------
// Kernel A: fused skip path, 2 pixels per thread, prefetch depth 2.
// ---------------------------------------------------------------------------
__global__ __launch_bounds__(128, 2)
void kA(const float* __restrict__ stage1,
        const float* __restrict__ w1, const float* __restrict__ g1, const float* __restrict__ b1,
        const float* __restrict__ w2, const float* __restrict__ g2, const float* __restrict__ b2,
        float* __restrict__ skip_out)
{
    __shared__ __align__(16) float w1T[64*64];   // [c][o]
    __shared__ __align__(16) float w2T[64*32];   // [o][s]
    __shared__ float sg1[64], sb1[64], sg2[32], sb2[32];
    int tid = threadIdx.x;
    for (int i = tid; i < 64*64; i += 128) { int o = i & 63, c = i >> 6; w1T[c*64+o] = w1[o*64+c]; }
    for (int i = tid; i < 64*32; i += 128) { int s = i & 31, o = i >> 5; w2T[o*32+s] = w2[s*64+o]; }
    if (tid < 64) { sg1[tid] = g1[tid]; sb1[tid] = b1[tid]; }
    if (tid < 32) { sg2[tid] = g2[tid]; sb2[tid] = b2[tid]; }
    __syncthreads();

    int gid = blockIdx.x * 256 + tid;
    int b = gid / HW1;
    int p = gid - b * HW1;
    const float* xin = stage1 + (size_t)b * 64 * HW1 + p;

    u64 acc[2][32];
    #pragma unroll
    for (int q = 0; q < 32; q++) { acc[0][q] = 0ull; acc[1][q] = 0ull; }

    const ulonglong2* w1T2 = (const ulonglong2*)w1T;
    // prefetch pipeline depth 2
    float p0a = xin[0],            p0b = xin[128];
    float p1a = xin[(size_t)1*HW1], p1b = xin[(size_t)1*HW1 + 128];
    for (int c = 0; c < 64; c++) {
        int cn = c + 2; if (cn > 63) cn = 63;
        float na = xin[(size_t)cn * HW1];
        float nb = xin[(size_t)cn * HW1 + 128];
        u64 x0 = pack2(p0a, p0a);
        u64 x1 = pack2(p0b, p0b);
        #pragma unroll
        for (int q = 0; q < 16; q++) {
            ulonglong2 wp = w1T2[c*16 + q];
            fma2(acc[0][q*2+0], x0, wp.x);
            fma2(acc[0][q*2+1], x0, wp.y);
            fma2(acc[1][q*2+0], x1, wp.x);
            fma2(acc[1][q*2+1], x1, wp.y);
        }
        p0a = p1a; p0b = p1b; p1a = na; p1b = nb;
    }

    const ulonglong2* w2T2 = (const ulonglong2*)w2T;
    #pragma unroll
    for (int px = 0; px < 2; px++) {
        u64 sacc2[16];
        #pragma unroll
        for (int s = 0; s < 16; s++) sacc2[s] = 0ull;
        #pragma unroll
        for (int q = 0; q < 32; q++) {
            float2 a = unpack2(acc[px][q]);
            int o = 2*q;
            float v0 = fmaxf(a.x * sg1[o]   + sb1[o],   0.f);
            float v1 = fmaxf(a.y * sg1[o+1] + sb1[o+1], 0.f);
            u64 v0p = pack2(v0, v0);
            u64 v1p = pack2(v1, v1);
            #pragma unroll
            for (int s4 = 0; s4 < 8; s4++) {
                ulonglong2 wp0 = w2T2[o*8 + s4];
                fma2(sacc2[s4*2+0], v0p, wp0.x);
                fma2(sacc2[s4*2+1], v0p, wp0.y);
            }
            #pragma unroll
            for (int s4 = 0; s4 < 8; s4++) {
                ulonglong2 wp1 = w2T2[(o+1)*8 + s4];
                fma2(sacc2[s4*2+0], v1p, wp1.x);
                fma2(sacc2[s4*2+1], v1p, wp1.y);
            }
        }
        float* op = skip_out + (size_t)b * 32 * HW1 + p + px * 128;
        #pragma unroll
        for (int s = 0; s < 16; s++) {
            float2 a = unpack2(sacc2[s]);
            op[(size_t)(2*s+0) * HW1] = fmaxf(a.x * sg2[2*s+0] + sb2[2*s+0], 0.f);
            op[(size_t)(2*s+1) * HW1] = fmaxf(a.y * sg2[2*s+1] + sb2[2*s+1], 0.f);
        }
    }
}

// ---------------------------------------------------------------------------
// Kernel B1: depth head. 48-channel GEMM + softmax depth + geometry.
// Prefetch pipeline depth 4.
// ---------------------------------------------------------------------------
__global__ __launch_bounds__(128, 4)
void kB1(const float* __restrict__ stage5,
         const float* __restrict__ wd, const float* __restrict__ gd, const float* __restrict__ bd,
         const float* __restrict__ intr, const float* __restrict__ extr)
{
    __shared__ __align__(16) float ws[64*48];
    __shared__ float sgd[48], sbd[48];
    int tid = threadIdx.x;
    if (tid < 48) { sgd[tid] = gd[tid]; sbd[tid] = bd[tid]; }
    int b = blockIdx.x / 88;
    int p = (blockIdx.x - b * 88) * 128 + tid;
    const float* xin = stage5 + (size_t)b * 512 * N5 + p;

    u64 acc2[24];
    #pragma unroll
    for (int i = 0; i < 24; i++) acc2[i] = 0ull;

    for (int c0 = 0; c0 < 512; c0 += 64) {
        __syncthreads();
        for (int i = tid; i < 64*48; i += 128) {
            int o = i % 48; int c = i / 48;
            ws[c*48 + o] = wd[o*512 + c0 + c];
        }
        __syncthreads();
        const ulonglong2* ws2 = (const ulonglong2*)ws;
        // prefetch pipeline depth 4
        float pf[4];
        #pragma unroll
        for (int d = 0; d < 4; d++) pf[d] = xin[(size_t)(c0 + d) * N5];
        for (int c = 0; c < 64; c++) {
            int gcn = c0 + c + 4; if (gcn > 511) gcn = 511;
            float nx = xin[(size_t)gcn * N5];
            u64 xv2 = pack2(pf[0], pf[0]);
            #pragma unroll
            for (int q = 0; q < 12; q++) {
                ulonglong2 wp = ws2[c*12 + q];
                fma2(acc2[q*2+0], xv2, wp.x);
                fma2(acc2[q*2+1], xv2, wp.y);
            }
            pf[0] = pf[1]; pf[1] = pf[2]; pf[2] = pf[3]; pf[3] = nx;
        }
    }

    float m = -1e30f;
    #pragma unroll
    for (int q = 0; q < 24; q++) {
        float2 a = unpack2(acc2[q]);
        int j = 2*q;
        m = fmaxf(m, fmaxf(10.f * (a.x * sgd[j] + sbd[j]),
                           10.f * (a.y * sgd[j+1] + sbd[j+1])));
    }
    const float lstep = 0.08711371545f;  // ln(60)/47
    float sum = 0.f, dsum = 0.f;
    #pragma unroll
    for (int q = 0; q < 24; q++) {
        float2 a = unpack2(acc2[q]);
        int j = 2*q;
        float l0 = 10.f * (a.x * sgd[j]   + sbd[j]);
        float l1 = 10.f * (a.y * sgd[j+1] + sbd[j+1]);
        float e0 = __expf(l0 - m);
        float e1 = __expf(l1 - m);
        sum  += e0 + e1;
        dsum += e0 * __expf((float)j * lstep) + e1 * __expf((float)(j+1) * lstep);
    }
    float depth = dsum / sum;
    depth = fminf(fmaxf(depth, 1.0f), 65.0f);

    const float* K = intr + b * 9;
    float a00=K[0],a01=K[1],a02=K[2],a10=K[3],a11=K[4],a12=K[5],a20=K[6],a21=K[7],a22=K[8];
    float det = a00*(a11*a22 - a12*a21) - a01*(a10*a22 - a12*a20) + a02*(a10*a21 - a11*a20);
    float id = 1.0f / det;
    float i00 = (a11*a22 - a12*a21) * id;
    float i01 = (a02*a21 - a01*a22) * id;
    float i02 = (a01*a12 - a02*a11) * id;
    float i10 = (a12*a20 - a10*a22) * id;
    float i11 = (a00*a22 - a02*a20) * id;
    float i12 = (a02*a10 - a00*a12) * id;
    float i20 = (a10*a21 - a11*a20) * id;
    float i21 = (a01*a20 - a00*a21) * id;
    float i22 = (a00*a11 - a01*a10) * id;

    float py = (float)(p / W5i);
    float px = (float)(p - (p / W5i) * W5i);
    float cx = depth * (i00*px + i01*py + i02);
    float cy = depth * (i10*px + i11*py + i12);
    float cz = depth * (i20*px + i21*py + i22);

    const float* T = extr + b * 16;
    float ex = T[0]*cx + T[1]*cy + T[2]*cz  + T[3];
    float ey = T[4]*cx + T[5]*cy + T[6]*cz  + T[7];
    float ez = T[8]*cx + T[9]*cy + T[10]*cz + T[11];

    bool ev = (ex >= -51.2f) & (ex < 51.2f) & (ey >= -51.2f) & (ey < 51.2f)
            & (ez >= -5.0f)  & (ez < 3.0f);
    int bx = (int)floorf(ex / 0.4f + 64.0f);
    int by = (int)floorf(ey / 0.4f + 64.0f);
    bool gv = (bx >= 0) & (bx < 128) & (by >= 0) & (by < 128);

    int idx = -1; float wf = 0.f;
    if (ev & gv) {
        idx = ((b * 128 + by) * 128 + bx) * BEVC;
        wf = __expf(-0.05f * fabsf(ez));
    }
    g_sidx[b * N5 + p] = idx;
    g_swf [b * N5 + p] = wf;
}

// ---------------------------------------------------------------------------
// Kernel B2: reduced-feature GEMM (64 out) + scatter-add, 2 pixels/thread.
// Prefetch pipeline depth 4.
// ---------------------------------------------------------------------------
__global__ __launch_bounds__(128, 2)
void kB2(const float* __restrict__ stage5,
         const float* __restrict__ w5, const float* __restrict__ g5, const float* __restrict__ b5)
{
    __shared__ __align__(16) float ws[64*64];   // [c][o]
    __shared__ float sg[64], sb[64];
    int tid = threadIdx.x;
    if (tid < 64) { sg[tid] = g5[tid]; sb[tid] = b5[tid]; }
    int b = blockIdx.x / 44;
    int p = (blockIdx.x - b * 44) * 256 + tid;
    const float* xin = stage5 + (size_t)b * 512 * N5 + p;

    u64 acc[2][32];
    #pragma unroll
    for (int q = 0; q < 32; q++) { acc[0][q] = 0ull; acc[1][q] = 0ull; }

    for (int c0 = 0; c0 < 512; c0 += 64) {
        __syncthreads();
        for (int i = tid; i < 64*64; i += 128) {
            int o = i & 63; int c = i >> 6;
            ws[c*64 + o] = w5[o*512 + c0 + c];
        }
        __syncthreads();
        const ulonglong2* ws2 = (const ulonglong2*)ws;
        // prefetch pipeline depth 4
        float pa[4], pb[4];
        #pragma unroll
        for (int d = 0; d < 4; d++) {
            pa[d] = xin[(size_t)(c0 + d) * N5];
            pb[d] = xin[(size_t)(c0 + d) * N5 + 128];
        }
        for (int c = 0; c < 64; c++) {
            int gcn = c0 + c + 4; if (gcn > 511) gcn = 511;
            float na = xin[(size_t)gcn * N5];
            float nb = xin[(size_t)gcn * N5 + 128];
            u64 x0 = pack2(pa[0], pa[0]);
            u64 x1 = pack2(pb[0], pb[0]);
            #pragma unroll
            for (int q = 0; q < 16; q++) {
                ulonglong2 wp = ws2[c*16 + q];
                fma2(acc[0][q*2+0], x0, wp.x);
                fma2(acc[0][q*2+1], x0, wp.y);
                fma2(acc[1][q*2+0], x1, wp.x);
                fma2(acc[1][q*2+1], x1, wp.y);
            }
            pa[0]=pa[1]; pa[1]=pa[2]; pa[2]=pa[3]; pa[3]=na;
            pb[0]=pb[1]; pb[1]=pb[2]; pb[2]=pb[3]; pb[3]=nb;
        }
    }

    #pragma unroll
    for (int px = 0; px < 2; px++) {
        int pp = p + px * 128;
        int idx = g_sidx[b * N5 + pp];
        float wf = g_swf[b * N5 + pp];
        if (idx >= 0) {
            float* cell = g_bev + idx;
            #pragma unroll
            for (int q = 0; q < 32; q++) {
                float2 a = unpack2(acc[px][q]);
                float r0 = fmaxf(a.x * sg[2*q+0] + sb[2*q+0], 0.f) * wf;
                float r1 = fmaxf(a.y * sg[2*q+1] + sb[2*q+1], 0.f) * wf;
                atomicAdd(cell + 2*q+0, r0);
                atomicAdd(cell + 2*q+1, r1);
            }
        }
    }
}

// ---------------------------------------------------------------------------
// Kernel C v4: 3x3 conv (64->128) + BN + ReLU.
// 32x16 tile, 2 px/thread, 32 oc/block, input channels chunked 2x32 so
// smem = 78K tile + 8K double-buffered per-kk weights -> 2 blocks/SM.
// ---------------------------------------------------------------------------
__global__ __launch_bounds__(256, 2)
void kC(const float* __restrict__ g, const float* __restrict__ bb,
        float* __restrict__ out)
{
    extern __shared__ __align__(16) float sm[];
    float* sin_ = sm;               // [ic 32][cell 612]  (18 x 34 tile)
    float* wbuf = sm + 32*612;      // [2][32ic * 32oc]
    int tid = threadIdx.x;
    int tx = tid & 31, ty = tid >> 5;        // ty 0..7
    int x0 = blockIdx.x * 32, y0 = blockIdx.y * 16;
    int bz = blockIdx.z;                     // 0..47
    int b = bz >> 2;
    int oc0 = (bz & 3) * 32;

    const float4* bev4 = (const float4*)g_bev;

    // --- load input tile for ic chunk 0 ---
    for (int i = tid; i < 612*8; i += 256) {
        int icg = i & 7;                 // float4 group 0..7 (chunk 0)
        int cell = i >> 3;
        int iy = cell / 34, ix = cell - iy * 34;
        int gy = y0 + iy - 1, gx = x0 + ix - 1;
        float4 v = make_float4(0.f, 0.f, 0.f, 0.f);
        if (gy >= 0 && gy < 128 && gx >= 0 && gx < 128)
            v = bev4[((((size_t)b * 128 + gy) * 128 + gx) << 4) + icg];
        sin_[(icg*4+0)*612 + cell] = v.x;
        sin_[(icg*4+1)*612 + cell] = v.y;
        sin_[(icg*4+2)*612 + cell] = v.z;
        sin_[(icg*4+3)*612 + cell] = v.w;
    }
    // --- stage weights for (chunk 0, kk 0) into wbuf[0] ---
    for (int i = tid; i < 1024; i += 256) {
        int icl = i >> 5, oc = i & 31;
        wbuf[i] = g_wt[(0*64 + 0*32 + icl)*128 + oc0 + oc];
    }
    __syncthreads();

    u64 acc[2][16];
    #pragma unroll
    for (int q = 0; q < 16; q++) { acc[0][q] = 0ull; acc[1][q] = 0ull; }

    for (int s = 0; s < 18; s++) {
        int buf = s & 1;
        if (s < 17) {
            int sn = s + 1;
            int kkn = (sn >= 9) ? sn - 9 : sn;
            int chn = (sn >= 9) ? 1 : 0;
            float* wdst = wbuf + (buf ^ 1) * 1024;
            for (int i = tid; i < 1024; i += 256) {
                int icl = i >> 5, oc = i & 31;
                wdst[i] = g_wt[(kkn*64 + chn*32 + icl)*128 + oc0 + oc];
            }
        }
        int kk = (s >= 9) ? s - 9 : s;
        int ky = kk / 3, kx = kk - ky*3;
        int base0 = (ty + ky) * 34 + tx + kx;
        int base1 = base0 + 8 * 34;
        const ulonglong2* wb = (const ulonglong2*)(wbuf + buf * 1024);
        #pragma unroll 4
        for (int ic = 0; ic < 32; ic++) {
            float xv0 = sin_[ic * 612 + base0];
            float xv1 = sin_[ic * 612 + base1];
            u64 x0p = pack2(xv0, xv0);
            u64 x1p = pack2(xv1, xv1);
            const ulonglong2* wrow = wb + ic*8;
            #pragma unroll
            for (int q = 0; q < 8; q++) {
                ulonglong2 wv = wrow[q];
                fma2(acc[0][2*q+0], x0p, wv.x);
                fma2(acc[0][2*q+1], x0p, wv.y);
                fma2(acc[1][2*q+0], x1p, wv.x);
                fma2(acc[1][2*q+1], x1p, wv.y);
            }
        }
        __syncthreads();
        if (s == 8) {
            // reload input tile for ic chunk 1 (all warps done with chunk 0)
            for (int i = tid; i < 612*8; i += 256) {
                int icg = (i & 7) + 8;          // float4 group 8..15 (chunk 1)
                int cell = i >> 3;
                int iy = cell / 34, ix = cell - iy * 34;
                int gy = y0 + iy - 1, gx = x0 + ix - 1;
                float4 v = make_float4(0.f, 0.f, 0.f, 0.f);
                if (gy >= 0 && gy < 128 && gx >= 0 && gx < 128)
                    v = bev4[((((size_t)b * 128 + gy) * 128 + gx) << 4) + icg];
                int icl = i & 7;
                sin_[(icl*4+0)*612 + cell] = v.x;
                sin_[(icl*4+1)*612 + cell] = v.y;
                sin_[(icl*4+2)*612 + cell] = v.z;
                sin_[(icl*4+3)*612 + cell] = v.w;
            }
            __syncthreads();
        }
    }

    #pragma unroll
    for (int px = 0; px < 2; px++) {
        float* op = out + (((size_t)b * 128 + oc0) * 128 + (y0 + ty + px*8)) * 128 + (x0 + tx);
        #pragma unroll
        for (int q = 0; q < 16; q++) {
            float2 a = unpack2(acc[px][q]);
            int o = 2*q;
            op[(size_t)(o+0) * 16384] = fmaxf(a.x * g[oc0 + o]     + bb[oc0 + o],     0.f);
            op[(size_t)(o+1) * 16384] = fmaxf(a.y * g[oc0 + o + 1] + bb[oc0 + o + 1], 0.f);
        }
    }
}

// ---------------------------------------------------------------------------
extern "C" void kernel_launch(void* const* d_in, const int* in_sizes, int n_in,
                              void* d_out, int out_size)
{
    const float* stage1 = (const float*)d_in[0];
    const float* stage5 = (const float*)d_in[1];
    const float* intr   = (const float*)d_in[2];
    const float* extr   = (const float*)d_in[3];
    const float* red1_w = (const float*)d_in[4];
    const float* red1_g = (const float*)d_in[5];
    const float* red1_b = (const float*)d_in[6];
    const float* skip_w = (const float*)d_in[7];
    const float* skip_g = (const float*)d_in[8];
    const float* skip_b = (const float*)d_in[9];
    const float* red5_w = (const float*)d_in[10];
    const float* red5_g = (const float*)d_in[11];
    const float* red5_b = (const float*)d_in[12];
    const float* dep5_w = (const float*)d_in[13];
    const float* dep5_g = (const float*)d_in[14];
    const float* dep5_b = (const float*)d_in[15];
    const float* main_w = (const float*)d_in[16];
    const float* main_g = (const float*)d_in[17];
    const float* main_b = (const float*)d_in[18];

    float* out_main = (float*)d_out;
    float* out_skip = (float*)d_out + OUT_MAIN;

    // side stream + events (created once; creation is not a captured op)
    static cudaStream_t s1 = nullptr;
    static cudaEvent_t eFork = nullptr, eJoin = nullptr;
    if (!s1) {
        cudaStreamCreateWithFlags(&s1, cudaStreamNonBlocking);
        cudaEventCreateWithFlags(&eFork, cudaEventDisableTiming);
        cudaEventCreateWithFlags(&eJoin, cudaEventDisableTiming);
    }

    // zero BEV scratch (critical path start)
    void* bevPtr = nullptr;
    cudaGetSymbolAddress(&bevPtr, g_bev);
    cudaMemsetAsync(bevPtr, 0, sizeof(float) * (size_t)Bn * 128 * 128 * BEVC);

    // fork: skip path runs concurrently on s1
    cudaEventRecord(eFork, 0);
    cudaStreamWaitEvent(s1, eFork, 0);
    kA<<<(Bn * HW1) / 256, 128, 0, s1>>>(stage1, red1_w, red1_g, red1_b,
                                         skip_w, skip_g, skip_b, out_skip);
    cudaEventRecord(eJoin, s1);

    // critical path on capture stream
    kWt<<<(9*64*128 + 255)/256, 256>>>(main_w);
    kB1<<<Bn * 88, 128>>>(stage5, dep5_w, dep5_g, dep5_b, intr, extr);
    kB2<<<Bn * 44, 128>>>(stage5, red5_w, red5_g, red5_b);

    // join before kC
    cudaStreamWaitEvent(0, eJoin, 0);

    // BEV conv v4: 2 blocks/SM
    int smem = (32*612 + 2*1024) * sizeof(float);   // 86528
    cudaFuncSetAttribute(kC, cudaFuncAttributeMaxDynamicSharedMemorySize, smem);
    dim3 gridC(4, 8, Bn * 4);
    kC<<<gridC, 256, smem>>>(main_g, main_b, out_main);
}

// round 14
// speedup vs baseline: 1.5504x; 1.1935x over previous
#include <cuda_runtime.h>
#include <math.h>

#define Bn 12
#define HW1 45056           // 128*352
#define N5 11264            // 64*176
#define W5i 176
#define BEVC 64
#define OUT_MAIN (12*128*128*128)   // 25165824

typedef unsigned long long u64;

// packed f32x2 helpers (sm_103a)
__device__ __forceinline__ u64 pack2(float lo, float hi) {
    u64 r; asm("mov.b64 %0, {%1, %2};" : "=l"(r) : "f"(lo), "f"(hi)); return r;
}
__device__ __forceinline__ void fma2(u64 &d, u64 a, u64 b) {
    asm("fma.rn.f32x2 %0, %1, %2, %0;" : "+l"(d) : "l"(a), "l"(b));
}
__device__ __forceinline__ float2 unpack2(u64 v) {
    float2 r; asm("mov.b64 {%0, %1}, %2;" : "=f"(r.x), "=f"(r.y) : "l"(v)); return r;
}

// BEV scratch, channels-last: [B][128][128][64]
__device__ float g_bev[Bn * 128 * 128 * BEVC];
__device__ int   g_sidx[Bn * N5];
__device__ float g_swf [Bn * N5];
// transposed weights
__device__ __align__(16) float g_wt [9 * 64 * 128];   // conv: [kk][ic][oc]
__device__ __align__(16) float g_w5t[512 * 64];       // red5: [c][o]
__device__ __align__(16) float g_wdt[512 * 48];       // dep5: [c][o]

// ---------------------------------------------------------------------------
// kWt: transpose conv + red5 + dep5 weights.  131072 = 512*256 elements.
// ---------------------------------------------------------------------------
__global__ void kWt(const float* __restrict__ w,
                    const float* __restrict__ w5, const float* __restrict__ wd)
{
    int i = blockIdx.x * 256 + threadIdx.x;
    if (i < 73728) {
        int oc = i & 127;
        int t  = i >> 7;
        int ic = t & 63;
        int kk = t >> 6;
        g_wt[i] = w[(oc*64 + ic)*9 + kk];
    } else if (i < 73728 + 32768) {
        int j = i - 73728;
        int o = j & 63, c = j >> 6;
        g_w5t[j] = w5[o*512 + c];
    } else if (i < 73728 + 32768 + 24576) {
        int j = i - 106496;
        int o = j % 48, c = j / 48;
        g_wdt[j] = wd[o*512 + c];
    }
}

// ---------------------------------------------------------------------------
// Kernel A: fused skip path, 2 px/thread, circular prefetch depth 4.
// ---------------------------------------------------------------------------
__global__ __launch_bounds__(128, 2)
void kA(const float* __restrict__ stage1,
        const float* __restrict__ w1, const float* __restrict__ g1, const float* __restrict__ b1,
        const float* __restrict__ w2, const float* __restrict__ g2, const float* __restrict__ b2,
        float* __restrict__ skip_out)
{
    __shared__ __align__(16) float w1T[64*64];   // [c][o]
    __shared__ __align__(16) float w2T[64*32];   // [o][s]
    __shared__ float sg1[64], sb1[64], sg2[32], sb2[32];
    int tid = threadIdx.x;
    for (int i = tid; i < 64*64; i += 128) { int o = i & 63, c = i >> 6; w1T[c*64+o] = w1[o*64+c]; }
    for (int i = tid; i < 64*32; i += 128) { int s = i & 31, o = i >> 5; w2T[o*32+s] = w2[s*64+o]; }
    if (tid < 64) { sg1[tid] = g1[tid]; sb1[tid] = b1[tid]; }
    if (tid < 32) { sg2[tid] = g2[tid]; sb2[tid] = b2[tid]; }
    __syncthreads();

    int gid = blockIdx.x * 256 + tid;
    int b = gid / HW1;
    int p = gid - b * HW1;
    const float* xin = stage1 + (size_t)b * 64 * HW1 + p;

    u64 acc[2][32];
    #pragma unroll
    for (int q = 0; q < 32; q++) { acc[0][q] = 0ull; acc[1][q] = 0ull; }

    const ulonglong2* w1T2 = (const ulonglong2*)w1T;
    float pa[4], pb[4];
    {
        const float* xp0 = xin;
        #pragma unroll
        for (int d = 0; d < 4; d++) { pa[d] = xp0[0]; pb[d] = xp0[128]; xp0 += HW1; }
    }
    const float* xp = xin + (size_t)4 * HW1;
    int ch = 4;
    for (int c = 0; c < 64; c += 4) {
        #pragma unroll
        for (int u = 0; u < 4; u++) {
            const float* xq = (ch < 64) ? xp : (xin + (size_t)63 * HW1);
            float na = xq[0], nb = xq[128];
            u64 x0 = pack2(pa[u], pa[u]);
            u64 x1 = pack2(pb[u], pb[u]);
            const ulonglong2* wrow = w1T2 + (c + u) * 16;
            #pragma unroll
            for (int q = 0; q < 16; q++) {
                ulonglong2 wp = wrow[q];
                fma2(acc[0][q*2+0], x0, wp.x);
                fma2(acc[0][q*2+1], x0, wp.y);
                fma2(acc[1][q*2+0], x1, wp.x);
                fma2(acc[1][q*2+1], x1, wp.y);
            }
            pa[u] = na; pb[u] = nb;
            xp += HW1; ch++;
        }
    }

    const ulonglong2* w2T2 = (const ulonglong2*)w2T;
    #pragma unroll
    for (int px = 0; px < 2; px++) {
        u64 sacc2[16];
        #pragma unroll
        for (int s = 0; s < 16; s++) sacc2[s] = 0ull;
        #pragma unroll
        for (int q = 0; q < 32; q++) {
            float2 a = unpack2(acc[px][q]);
            int o = 2*q;
            float v0 = fmaxf(a.x * sg1[o]   + sb1[o],   0.f);
            float v1 = fmaxf(a.y * sg1[o+1] + sb1[o+1], 0.f);
            u64 v0p = pack2(v0, v0);
            u64 v1p = pack2(v1, v1);
            #pragma unroll
            for (int s4 = 0; s4 < 8; s4++) {
                ulonglong2 wp0 = w2T2[o*8 + s4];
                fma2(sacc2[s4*2+0], v0p, wp0.x);
                fma2(sacc2[s4*2+1], v0p, wp0.y);
            }
            #pragma unroll
            for (int s4 = 0; s4 < 8; s4++) {
                ulonglong2 wp1 = w2T2[(o+1)*8 + s4];
                fma2(sacc2[s4*2+0], v1p, wp1.x);
                fma2(sacc2[s4*2+1], v1p, wp1.y);
            }
        }
        float* op = skip_out + (size_t)b * 32 * HW1 + p + px * 128;
        #pragma unroll
        for (int s = 0; s < 16; s++) {
            float2 a = unpack2(sacc2[s]);
            op[(size_t)(2*s+0) * HW1] = fmaxf(a.x * sg2[2*s+0] + sb2[2*s+0], 0.f);
            op[(size_t)(2*s+1) * HW1] = fmaxf(a.y * sg2[2*s+1] + sb2[2*s+1], 0.f);
        }
    }
}

// ---------------------------------------------------------------------------
// Kernel B1: depth head.  Circular prefetch depth 4, float4 weight staging.
// ---------------------------------------------------------------------------
__global__ __launch_bounds__(128, 4)
void kB1(const float* __restrict__ stage5,
         const float* __restrict__ gd, const float* __restrict__ bd,
         const float* __restrict__ intr, const float* __restrict__ extr)
{
    __shared__ __align__(16) float ws[64*48];
    __shared__ float sgd[48], sbd[48];
    int tid = threadIdx.x;
    if (tid < 48) { sgd[tid] = gd[tid]; sbd[tid] = bd[tid]; }
    int b = blockIdx.x / 88;
    int p = (blockIdx.x - b * 88) * 128 + tid;
    const float* xin = stage5 + (size_t)b * 512 * N5 + p;

    u64 acc2[24];
    #pragma unroll
    for (int i = 0; i < 24; i++) acc2[i] = 0ull;

    for (int c0 = 0; c0 < 512; c0 += 64) {
        __syncthreads();
        {
            const float4* src = (const float4*)(g_wdt + c0*48);
            float4* dst = (float4*)ws;
            for (int i = tid; i < 768; i += 128) dst[i] = src[i];
        }
        __syncthreads();
        const ulonglong2* ws2 = (const ulonglong2*)ws;
        float pf[4];
        {
            const float* xp0 = xin + (size_t)c0 * N5;
            #pragma unroll
            for (int d = 0; d < 4; d++) { pf[d] = xp0[0]; xp0 += N5; }
        }
        const float* xp = xin + (size_t)(c0 + 4) * N5;
        int ch = c0 + 4;
        for (int c = 0; c < 64; c += 4) {
            #pragma unroll
            for (int u = 0; u < 4; u++) {
                const float* xq = (ch < 512) ? xp : (xin + (size_t)511 * N5);
                float nx = xq[0];
                u64 xv2 = pack2(pf[u], pf[u]);
                const ulonglong2* wrow = ws2 + (c + u) * 12;
                #pragma unroll
                for (int q = 0; q < 12; q++) {
                    ulonglong2 wp = wrow[q];
                    fma2(acc2[q*2+0], xv2, wp.x);
                    fma2(acc2[q*2+1], xv2, wp.y);
                }
                pf[u] = nx;
                xp += N5; ch++;
            }
        }
    }

    float m = -1e30f;
    #pragma unroll
    for (int q = 0; q < 24; q++) {
        float2 a = unpack2(acc2[q]);
        int j = 2*q;
        m = fmaxf(m, fmaxf(10.f * (a.x * sgd[j] + sbd[j]),
                           10.f * (a.y * sgd[j+1] + sbd[j+1])));
    }
    const float lstep = 0.08711371545f;  // ln(60)/47
    float sum = 0.f, dsum = 0.f;
    #pragma unroll
    for (int q = 0; q < 24; q++) {
        float2 a = unpack2(acc2[q]);
        int j = 2*q;
        float l0 = 10.f * (a.x * sgd[j]   + sbd[j]);
        float l1 = 10.f * (a.y * sgd[j+1] + sbd[j+1]);
        float e0 = __expf(l0 - m);
        float e1 = __expf(l1 - m);
        sum  += e0 + e1;
        dsum += e0 * __expf((float)j * lstep) + e1 * __expf((float)(j+1) * lstep);
    }
    float depth = dsum / sum;
    depth = fminf(fmaxf(depth, 1.0f), 65.0f);

    const float* K = intr + b * 9;
    float a00=K[0],a01=K[1],a02=K[2],a10=K[3],a11=K[4],a12=K[5],a20=K[6],a21=K[7],a22=K[8];
    float det = a00*(a11*a22 - a12*a21) - a01*(a10*a22 - a12*a20) + a02*(a10*a21 - a11*a20);
    float id = 1.0f / det;
    float i00 = (a11*a22 - a12*a21) * id;
    float i01 = (a02*a21 - a01*a22) * id;
    float i02 = (a01*a12 - a02*a11) * id;
    float i10 = (a12*a20 - a10*a22) * id;
    float i11 = (a00*a22 - a02*a20) * id;
    float i12 = (a02*a10 - a00*a12) * id;
    float i20 = (a10*a21 - a11*a20) * id;
    float i21 = (a01*a20 - a00*a21) * id;
    float i22 = (a00*a11 - a01*a10) * id;

    float py = (float)(p / W5i);
    float px = (float)(p - (p / W5i) * W5i);
    float cx = depth * (i00*px + i01*py + i02);
    float cy = depth * (i10*px + i11*py + i12);
    float cz = depth * (i20*px + i21*py + i22);

    const float* T = extr + b * 16;
    float ex = T[0]*cx + T[1]*cy + T[2]*cz  + T[3];
    float ey = T[4]*cx + T[5]*cy + T[6]*cz  + T[7];
    float ez = T[8]*cx + T[9]*cy + T[10]*cz + T[11];

    bool ev = (ex >= -51.2f) & (ex < 51.2f) & (ey >= -51.2f) & (ey < 51.2f)
            & (ez >= -5.0f)  & (ez < 3.0f);
    int bx = (int)floorf(ex / 0.4f + 64.0f);
    int by = (int)floorf(ey / 0.4f + 64.0f);
    bool gv = (bx >= 0) & (bx < 128) & (by >= 0) & (by < 128);

    int idx = -1; float wf = 0.f;
    if (ev & gv) {
        idx = ((b * 128 + by) * 128 + bx) * BEVC;
        wf = __expf(-0.05f * fabsf(ez));
    }
    g_sidx[b * N5 + p] = idx;
    g_swf [b * N5 + p] = wf;
}

// ---------------------------------------------------------------------------
// Kernel B2: reduced GEMM + scatter, 2 px/thread, circular prefetch depth 4,
// float4 weight staging from pre-transposed g_w5t.
// ---------------------------------------------------------------------------
__global__ __launch_bounds__(128, 2)
void kB2(const float* __restrict__ stage5,
         const float* __restrict__ g5, const float* __restrict__ b5)
{
    __shared__ __align__(16) float ws[64*64];   // [c][o]
    __shared__ float sg[64], sb[64];
    int tid = threadIdx.x;
    if (tid < 64) { sg[tid] = g5[tid]; sb[tid] = b5[tid]; }
    int b = blockIdx.x / 44;
    int p = (blockIdx.x - b * 44) * 256 + tid;
    const float* xin = stage5 + (size_t)b * 512 * N5 + p;

    u64 acc[2][32];
    #pragma unroll
    for (int q = 0; q < 32; q++) { acc[0][q] = 0ull; acc[1][q] = 0ull; }

    for (int c0 = 0; c0 < 512; c0 += 64) {
        __syncthreads();
        {
            const float4* src = (const float4*)(g_w5t + (c0 << 6));
            float4* dst = (float4*)ws;
            for (int i = tid; i < 1024; i += 128) dst[i] = src[i];
        }
        __syncthreads();
        const ulonglong2* ws2 = (const ulonglong2*)ws;
        float pa[4], pb[4];
        {
            const float* xp0 = xin + (size_t)c0 * N5;
            #pragma unroll
            for (int d = 0; d < 4; d++) { pa[d] = xp0[0]; pb[d] = xp0[128]; xp0 += N5; }
        }
        const float* xp = xin + (size_t)(c0 + 4) * N5;
        int ch = c0 + 4;
        for (int c = 0; c < 64; c += 4) {
            #pragma unroll
            for (int u = 0; u < 4; u++) {
                const float* xq = (ch < 512) ? xp : (xin + (size_t)511 * N5);
                float na = xq[0], nb = xq[128];
                u64 x0 = pack2(pa[u], pa[u]);
                u64 x1 = pack2(pb[u], pb[u]);
                const ulonglong2* wrow = ws2 + (c + u) * 16;
                #pragma unroll
                for (int q = 0; q < 16; q++) {
                    ulonglong2 wp = wrow[q];
                    fma2(acc[0][q*2+0], x0, wp.x);
                    fma2(acc[0][q*2+1], x0, wp.y);
                    fma2(acc[1][q*2+0], x1, wp.x);
                    fma2(acc[1][q*2+1], x1, wp.y);
                }
                pa[u] = na; pb[u] = nb;
                xp += N5; ch++;
            }
        }
    }

    #pragma unroll
    for (int px = 0; px < 2; px++) {
        int pp = p + px * 128;
        int idx = g_sidx[b * N5 + pp];
        float wf = g_swf[b * N5 + pp];
        if (idx >= 0) {
            float* cell = g_bev + idx;
            #pragma unroll
            for (int q = 0; q < 32; q++) {
                float2 a = unpack2(acc[px][q]);
                float r0 = fmaxf(a.x * sg[2*q+0] + sb[2*q+0], 0.f) * wf;
                float r1 = fmaxf(a.y * sg[2*q+1] + sb[2*q+1], 0.f) * wf;
                atomicAdd(cell + 2*q+0, r0);
                atomicAdd(cell + 2*q+1, r1);
            }
        }
    }
}

// ---------------------------------------------------------------------------
// Kernel C v4: 3x3 conv (64->128) + BN + ReLU.  (unchanged from R12/R13)
// ---------------------------------------------------------------------------
__global__ __launch_bounds__(256, 2)
void kC(const float* __restrict__ g, const float* __restrict__ bb,
        float* __restrict__ out)
{
    extern __shared__ __align__(16) float sm[];
    float* sin_ = sm;               // [ic 32][cell 612]  (18 x 34 tile)
    float* wbuf = sm + 32*612;      // [2][32ic * 32oc]
    int tid = threadIdx.x;
    int tx = tid & 31, ty = tid >> 5;        // ty 0..7
    int x0 = blockIdx.x * 32, y0 = blockIdx.y * 16;
    int bz = blockIdx.z;                     // 0..47
    int b = bz >> 2;
    int oc0 = (bz & 3) * 32;

    const float4* bev4 = (const float4*)g_bev;

    for (int i = tid; i < 612*8; i += 256) {
        int icg = i & 7;
        int cell = i >> 3;
        int iy = cell / 34, ix = cell - iy * 34;
        int gy = y0 + iy - 1, gx = x0 + ix - 1;
        float4 v = make_float4(0.f, 0.f, 0.f, 0.f);
        if (gy >= 0 && gy < 128 && gx >= 0 && gx < 128)
            v = bev4[((((size_t)b * 128 + gy) * 128 + gx) << 4) + icg];
        sin_[(icg*4+0)*612 + cell] = v.x;
        sin_[(icg*4+1)*612 + cell] = v.y;
        sin_[(icg*4+2)*612 + cell] = v.z;
        sin_[(icg*4+3)*612 + cell] = v.w;
    }
    for (int i = tid; i < 1024; i += 256) {
        int icl = i >> 5, oc = i & 31;
        wbuf[i] = g_wt[(0*64 + 0*32 + icl)*128 + oc0 + oc];
    }
    __syncthreads();

    u64 acc[2][16];
    #pragma unroll
    for (int q = 0; q < 16; q++) { acc[0][q] = 0ull; acc[1][q] = 0ull; }

    for (int s = 0; s < 18; s++) {
        int buf = s & 1;
        if (s < 17) {
            int sn = s + 1;
            int kkn = (sn >= 9) ? sn - 9 : sn;
            int chn = (sn >= 9) ? 1 : 0;
            float* wdst = wbuf + (buf ^ 1) * 1024;
            for (int i = tid; i < 1024; i += 256) {
                int icl = i >> 5, oc = i & 31;
                wdst[i] = g_wt[(kkn*64 + chn*32 + icl)*128 + oc0 + oc];
            }
        }
        int kk = (s >= 9) ? s - 9 : s;
        int ky = kk / 3, kx = kk - ky*3;
        int base0 = (ty + ky) * 34 + tx + kx;
        int base1 = base0 + 8 * 34;
        const ulonglong2* wb = (const ulonglong2*)(wbuf + buf * 1024);
        #pragma unroll 4
        for (int ic = 0; ic < 32; ic++) {
            float xv0 = sin_[ic * 612 + base0];
            float xv1 = sin_[ic * 612 + base1];
            u64 x0p = pack2(xv0, xv0);
            u64 x1p = pack2(xv1, xv1);
            const ulonglong2* wrow = wb + ic*8;
            #pragma unroll
            for (int q = 0; q < 8; q++) {
                ulonglong2 wv = wrow[q];
                fma2(acc[0][2*q+0], x0p, wv.x);
                fma2(acc[0][2*q+1], x0p, wv.y);
                fma2(acc[1][2*q+0], x1p, wv.x);
                fma2(acc[1][2*q+1], x1p, wv.y);
            }
        }
        __syncthreads();
        if (s == 8) {
            for (int i = tid; i < 612*8; i += 256) {
                int icg = (i & 7) + 8;
                int cell = i >> 3;
                int iy = cell / 34, ix = cell - iy * 34;
                int gy = y0 + iy - 1, gx = x0 + ix - 1;
                float4 v = make_float4(0.f, 0.f, 0.f, 0.f);
                if (gy >= 0 && gy < 128 && gx >= 0 && gx < 128)
                    v = bev4[((((size_t)b * 128 + gy) * 128 + gx) << 4) + icg];
                int icl = i & 7;
                sin_[(icl*4+0)*612 + cell] = v.x;
                sin_[(icl*4+1)*612 + cell] = v.y;
                sin_[(icl*4+2)*612 + cell] = v.z;
                sin_[(icl*4+3)*612 + cell] = v.w;
            }
            __syncthreads();
        }
    }

    #pragma unroll
    for (int px = 0; px < 2; px++) {
        float* op = out + (((size_t)b * 128 + oc0) * 128 + (y0 + ty + px*8)) * 128 + (x0 + tx);
        #pragma unroll
        for (int q = 0; q < 16; q++) {
            float2 a = unpack2(acc[px][q]);
            int o = 2*q;
            op[(size_t)(o+0) * 16384] = fmaxf(a.x * g[oc0 + o]     + bb[oc0 + o],     0.f);
            op[(size_t)(o+1) * 16384] = fmaxf(a.y * g[oc0 + o + 1] + bb[oc0 + o + 1], 0.f);
        }
    }
}

// ---------------------------------------------------------------------------
extern "C" void kernel_launch(void* const* d_in, const int* in_sizes, int n_in,
                              void* d_out, int out_size)
{
    const float* stage1 = (const float*)d_in[0];
    const float* stage5 = (const float*)d_in[1];
    const float* intr   = (const float*)d_in[2];
    const float* extr   = (const float*)d_in[3];
    const float* red1_w = (const float*)d_in[4];
    const float* red1_g = (const float*)d_in[5];
    const float* red1_b = (const float*)d_in[6];
    const float* skip_w = (const float*)d_in[7];
    const float* skip_g = (const float*)d_in[8];
    const float* skip_b = (const float*)d_in[9];
    const float* red5_w = (const float*)d_in[10];
    const float* red5_g = (const float*)d_in[11];
    const float* red5_b = (const float*)d_in[12];
    const float* dep5_w = (const float*)d_in[13];
    const float* dep5_g = (const float*)d_in[14];
    const float* dep5_b = (const float*)d_in[15];
    const float* main_w = (const float*)d_in[16];
    const float* main_g = (const float*)d_in[17];
    const float* main_b = (const float*)d_in[18];

    float* out_main = (float*)d_out;
    float* out_skip = (float*)d_out + OUT_MAIN;

    // side stream + events (created once; creation is not a captured op)
    static cudaStream_t s1 = nullptr;
    static cudaEvent_t eFork = nullptr, eJoin = nullptr;
    if (!s1) {
        cudaStreamCreateWithFlags(&s1, cudaStreamNonBlocking);
        cudaEventCreateWithFlags(&eFork, cudaEventDisableTiming);
        cudaEventCreateWithFlags(&eJoin, cudaEventDisableTiming);
    }

    // zero BEV scratch (critical path start)
    void* bevPtr = nullptr;
    cudaGetSymbolAddress(&bevPtr, g_bev);
    cudaMemsetAsync(bevPtr, 0, sizeof(float) * (size_t)Bn * 128 * 128 * BEVC);

    // fork: skip path runs concurrently on s1
    cudaEventRecord(eFork, 0);
    cudaStreamWaitEvent(s1, eFork, 0);
    kA<<<(Bn * HW1) / 256, 128, 0, s1>>>(stage1, red1_w, red1_g, red1_b,
                                         skip_w, skip_g, skip_b, out_skip);
    cudaEventRecord(eJoin, s1);

    // critical path on capture stream
    kWt<<<512, 256>>>(main_w, red5_w, dep5_w);
    kB1<<<Bn * 88, 128>>>(stage5, dep5_g, dep5_b, intr, extr);
    kB2<<<Bn * 44, 128>>>(stage5, red5_g, red5_b);

    // join before kC
    cudaStreamWaitEvent(0, eJoin, 0);

    // BEV conv v4: 2 blocks/SM
    int smem = (32*612 + 2*1024) * sizeof(float);   // 86528
    cudaFuncSetAttribute(kC, cudaFuncAttributeMaxDynamicSharedMemorySize, smem);
    dim3 gridC(4, 8, Bn * 4);
    kC<<<gridC, 256, smem>>>(main_g, main_b, out_main);
}